// round 12
// baseline (speedup 1.0000x reference)
#include <cuda_runtime.h>
#include <cuda_bf16.h>
#include <math.h>
#include <stdint.h>

#define NB 128
#define ND 64
#define NL0 4096
#define NL1 2048
#define NL2 1024
#define NL3 512

// Scratch (static device allocations allowed; cudaMalloc is not)
__device__ float g_pe[NL0 * ND];                          // 1 MB positional table
__device__ float g_w1t[256 * 64];                         // W1 transposed [k=kk*64+ci][co]
__device__ float g_weff[3][64][12];                       // composed 12-tap conv weights (3 edge cases)
__device__ float g_tbp[4][64];                            // per-kk token-bias projection through W1
__device__ float g_tt[NL1 * 64];                          // TT[p][co] = W1*pe + W1*tb + b1 (case-aware)
__device__ __nv_bfloat16 g_wtb[3][2][64 * 264];           // W hi/lo planes, row stride 264 bf16 (528B)
__device__ __nv_bfloat16 g_h1b[2][(size_t)NB * NL1 * ND]; // h1 as bf16 hi/lo planes
__device__ __nv_bfloat16 g_h2b[2][(size_t)NB * NL2 * ND]; // h2 as bf16 hi/lo planes

__device__ __forceinline__ uint32_t smem_u32(const void* p) {
    uint32_t a;
    asm("{ .reg .u64 t; cvta.to.shared.u64 t, %1; cvt.u32.u64 %0, t; }" : "=r"(a) : "l"(p));
    return a;
}
__device__ __forceinline__ void ldsm4(uint32_t* r, uint32_t a) {
    asm volatile("ldmatrix.sync.aligned.m8n8.x4.shared.b16 {%0,%1,%2,%3}, [%4];"
                 : "=r"(r[0]), "=r"(r[1]), "=r"(r[2]), "=r"(r[3]) : "r"(a));
}
__device__ __forceinline__ void mma16816(float* c, const uint32_t* a, const uint32_t* b) {
    asm volatile("mma.sync.aligned.m16n8k16.row.col.f32.bf16.bf16.f32 "
                 "{%0,%1,%2,%3}, {%4,%5,%6,%7}, {%8,%9}, {%0,%1,%2,%3};"
                 : "+f"(c[0]), "+f"(c[1]), "+f"(c[2]), "+f"(c[3])
                 : "r"(a[0]), "r"(a[1]), "r"(a[2]), "r"(a[3]), "r"(b[0]), "r"(b[1]));
}

// ---------------------------------------------------------------------------
// Positional embedding table (double precision to match the reference's fp32
// rounding chain; avoids sinf large-arg reduction error).
// ---------------------------------------------------------------------------
__global__ void pe_kernel() {
    int idx = blockIdx.x * blockDim.x + threadIdx.x;
    if (idx >= NL0 * 32) return;
    int l = idx >> 5, i = idx & 31;
    float argf = (float)(2 * i) * (float)(-log(10000.0) / 64.0);
    float divf = (float)exp((double)argf);
    float angf = (float)l * divf;
    double ang = (double)angf;
    g_pe[l * ND + 2 * i]     = (float)sin(ang);
    g_pe[l * ND + 2 * i + 1] = (float)cos(ang);
}

// ---------------------------------------------------------------------------
// Stage-conv weights (co, ci, kk) -> bf16 hi/lo planes at W[co][k=kk*64+ci],
// row stride 264 bf16 (528B -> ldmatrix conflict-free).
// ---------------------------------------------------------------------------
__global__ void wt_kernel(const float* __restrict__ w2,
                          const float* __restrict__ w3) {
    int idx = blockIdx.x * blockDim.x + threadIdx.x;
    if (idx >= 2 * 64 * 64 * 4) return;
    int s = idx / 16384;                  // 0 -> stage2, 1 -> stage3
    int rem = idx - s * 16384;            // co*256 + ci*4 + kk
    int co = rem >> 8;
    int ci = (rem >> 2) & 63;
    int kk = rem & 3;
    const float* w = (s == 0) ? w2 : w3;
    float v = w[rem];
    __nv_bfloat16 hi = __float2bfloat16(v);
    __nv_bfloat16 lo = __float2bfloat16(v - __bfloat162float(hi));
    int off = co * 264 + kk * 64 + ci;
    g_wtb[s + 1][0][off] = hi;
    g_wtb[s + 1][1][off] = lo;
}

// ---------------------------------------------------------------------------
// W1 transpose for the TT build: g_w1t[(kk*64+ci)*64 + co] = w1[co,ci,kk]
// ---------------------------------------------------------------------------
__global__ void w1t_kernel(const float* __restrict__ w1) {
    int idx = blockIdx.x * blockDim.x + threadIdx.x;
    if (idx >= 16384) return;
    int co = idx >> 8;
    int ci = (idx >> 2) & 63;
    int kk = idx & 3;
    g_w1t[(kk * 64 + ci) * 64 + co] = w1[idx];
}

// ---------------------------------------------------------------------------
// Composed front weights:
//   Weff[case][co][tau] = sum_{kk in valid(case), ci, t: t = tau-4-kk+pad_ci}
//                         W1[co,ci,kk] * tokw_ci[t]
// cases: 0 interior (all kk), 1 p==0 (kk=0 dropped), 2 p==L-1 (kk=3 dropped).
// Also g_tbp[kk][co] = sum_ci W1[co,ci,kk] * tok_bias[ci].
// ---------------------------------------------------------------------------
__global__ void weff_kernel(const float* __restrict__ w1,
                            const float* __restrict__ tw3, const float* __restrict__ tb3,
                            const float* __restrict__ tw5, const float* __restrict__ tb5,
                            const float* __restrict__ tw7, const float* __restrict__ tb7,
                            const float* __restrict__ tw9, const float* __restrict__ tb9) {
    int idx = blockIdx.x * blockDim.x + threadIdx.x;
    if (idx < 2304) {
        int cse = idx / 768;
        int rem = idx - cse * 768;
        int co = rem / 12, tau = rem - co * 12;
        float acc = 0.f;
        for (int kk = 0; kk < 4; ++kk) {
            if (cse == 1 && kk == 0) continue;
            if (cse == 2 && kk == 3) continue;
            for (int ci = 0; ci < 64; ++ci) {
                int g = ci & 3, j = ci >> 2;
                int pad = g + 1, ks = 3 + 2 * g;
                int t = tau - 4 - kk + pad;
                if (t < 0 || t >= ks) continue;
                const float* tw = (g == 0) ? tw3 : (g == 1) ? tw5 : (g == 2) ? tw7 : tw9;
                acc += w1[co * 256 + ci * 4 + kk] * tw[j * ks + t];
            }
        }
        g_weff[cse][co][tau] = acc;
    } else if (idx < 2560) {
        int r = idx - 2304;
        int kk = r >> 6, co = r & 63;
        float acc = 0.f;
        for (int ci = 0; ci < 64; ++ci) {
            int g = ci & 3;
            const float* tbp = (g == 0) ? tb3 : (g == 1) ? tb5 : (g == 2) ? tb7 : tb9;
            acc += w1[co * 256 + ci * 4 + kk] * tbp[ci >> 2];
        }
        g_tbp[kk][co] = acc;
    }
}

// ---------------------------------------------------------------------------
// TT[p][co] = b1[co] + sum_{kk valid} ( tbp[kk][co] + sum_ci W1[co,ci,kk]*pe[2p-1+kk][ci] )
// 128 blocks x 256 threads; block covers 16 positions. W1T + pe rows in smem.
// ---------------------------------------------------------------------------
__global__ void tt_kernel(const float* __restrict__ cb1) {
    extern __shared__ float sm[];
    float* w1ts = sm;              // 16384
    float* pes  = sm + 16384;      // 34*64
    int tid = threadIdx.x;
    int p0 = blockIdx.x * 16;
    for (int i = tid; i < 16384; i += 256) w1ts[i] = g_w1t[i];
    for (int i = tid; i < 34 * 64; i += 256) {
        int r = i >> 6, ci = i & 63;
        int g = 2 * p0 - 1 + r;
        pes[i] = (g >= 0 && g < NL0) ? g_pe[g * 64 + ci] : 0.f;
    }
    __syncthreads();
    int co = tid & 63, py = tid >> 6;
    float acc[4] = {0.f, 0.f, 0.f, 0.f};
    for (int kk = 0; kk < 4; ++kk) {
#pragma unroll 8
        for (int ci = 0; ci < 64; ++ci) {
            float w = w1ts[(kk * 64 + ci) * 64 + co];
#pragma unroll
            for (int i = 0; i < 4; ++i)
                acc[i] += w * pes[(2 * (py * 4 + i) + kk) * 64 + ci];
        }
    }
    float tsum = g_tbp[0][co] + g_tbp[1][co] + g_tbp[2][co] + g_tbp[3][co];
    float bb = cb1[co];
#pragma unroll
    for (int i = 0; i < 4; ++i) {
        int p = p0 + py * 4 + i;
        float bias = bb + tsum;
        if (p == 0)       bias -= g_tbp[0][co];
        if (p == NL1 - 1) bias -= g_tbp[3][co];
        g_tt[p * 64 + co] = acc[i] + bias;
    }
}

// ---------------------------------------------------------------------------
// Stage1 "front": out1[p][co] = tanh( conv12(Weff, x)[p][co] + TT[p][co] ), LN,
// written as bf16 hi/lo planes. Thread = 4 co x 8 positions; LN via 16-lane shfl.
// Grid (8, NB); 512 threads; tile 256 positions.
// ---------------------------------------------------------------------------
__global__ void __launch_bounds__(512)
front_kernel(const float* __restrict__ x,
             __nv_bfloat16* __restrict__ outhi, __nv_bfloat16* __restrict__ outlo,
             const float* __restrict__ lng, const float* __restrict__ lnb) {
    __shared__ float xs[522];
    __shared__ float wsm[768];
    __shared__ float gsm[64], lbsm[64];
    int tid = threadIdx.x;
    int t = blockIdx.x, b = blockIdx.y;
    int p0 = t * 256;
    if (tid < 64) { gsm[tid] = lng[tid]; lbsm[tid] = lnb[tid]; }
    for (int i = tid; i < 768; i += 512) wsm[i] = ((const float*)g_weff)[i]; // case 0
    const float* xb = x + (size_t)b * NL0;
    int base = 2 * p0 - 5;
    for (int i = tid; i < 522; i += 512) {
        int gi = base + i;
        xs[i] = (gi >= 0 && gi < NL0) ? xb[gi] : 0.f;
    }
    __syncthreads();

    int tx = tid & 15, ty = tid >> 4;
    int co0 = tx * 4;
    float wr[4][12];
#pragma unroll
    for (int c = 0; c < 4; ++c)
#pragma unroll
        for (int tau = 0; tau < 12; ++tau) wr[c][tau] = wsm[(co0 + c) * 12 + tau];
    float xr[26];
#pragma unroll
    for (int i = 0; i < 26; ++i) xr[i] = xs[16 * ty + i];

    float acc[8][4];
#pragma unroll
    for (int j = 0; j < 8; ++j) {
#pragma unroll
        for (int c = 0; c < 4; ++c) acc[j][c] = 0.f;
#pragma unroll
        for (int tau = 0; tau < 12; ++tau) {
            float xv = xr[2 * j + tau];
#pragma unroll
            for (int c = 0; c < 4; ++c) acc[j][c] = fmaf(wr[c][tau], xv, acc[j][c]);
        }
    }
    // edge positions use case-1 / case-2 composed weights
    if (t == 0 && ty == 0) {
#pragma unroll
        for (int c = 0; c < 4; ++c) {
            float a = 0.f;
            for (int tau = 0; tau < 12; ++tau) a = fmaf(g_weff[1][co0 + c][tau], xr[tau], a);
            acc[0][c] = a;
        }
    }
    if (t == 7 && ty == 31) {
#pragma unroll
        for (int c = 0; c < 4; ++c) {
            float a = 0.f;
            for (int tau = 0; tau < 12; ++tau) a = fmaf(g_weff[2][co0 + c][tau], xr[14 + tau], a);
            acc[7][c] = a;
        }
    }

#pragma unroll
    for (int j = 0; j < 8; ++j) {
        int p = p0 + ty * 8 + j;
        float4 tt4 = *(const float4*)(g_tt + p * 64 + co0);
        float v0 = tanhf(acc[j][0] + tt4.x);
        float v1 = tanhf(acc[j][1] + tt4.y);
        float v2 = tanhf(acc[j][2] + tt4.z);
        float v3 = tanhf(acc[j][3] + tt4.w);
        float s1 = v0 + v1 + v2 + v3;
        float s2 = v0 * v0 + v1 * v1 + v2 * v2 + v3 * v3;
#pragma unroll
        for (int o = 1; o < 16; o <<= 1) {
            s1 += __shfl_xor_sync(0xffffffffu, s1, o);
            s2 += __shfl_xor_sync(0xffffffffu, s2, o);
        }
        float m   = s1 * (1.f / 64.f);
        float var = s2 * (1.f / 64.f) - m * m;
        float inv = 1.f / sqrtf(var + 1e-5f);
        float o0 = (v0 - m) * inv * gsm[co0 + 0] + lbsm[co0 + 0];
        float o1 = (v1 - m) * inv * gsm[co0 + 1] + lbsm[co0 + 1];
        float o2 = (v2 - m) * inv * gsm[co0 + 2] + lbsm[co0 + 2];
        float o3 = (v3 - m) * inv * gsm[co0 + 3] + lbsm[co0 + 3];
        size_t ro = ((size_t)b * NL1 + p) * ND + co0;
        __nv_bfloat16 h0 = __float2bfloat16(o0);
        __nv_bfloat16 h1 = __float2bfloat16(o1);
        __nv_bfloat16 h2 = __float2bfloat16(o2);
        __nv_bfloat16 h3 = __float2bfloat16(o3);
        *(__nv_bfloat162*)(outhi + ro)     = __nv_bfloat162(h0, h1);
        *(__nv_bfloat162*)(outhi + ro + 2) = __nv_bfloat162(h2, h3);
        *(__nv_bfloat162*)(outlo + ro)     = __nv_bfloat162(
            __float2bfloat16(o0 - __bfloat162float(h0)),
            __float2bfloat16(o1 - __bfloat162float(h1)));
        *(__nv_bfloat162*)(outlo + ro + 2) = __nv_bfloat162(
            __float2bfloat16(o2 - __bfloat162float(h2)),
            __float2bfloat16(o3 - __bfloat162float(h3)));
    }
}

// ---------------------------------------------------------------------------
// Stages 2/3 as mma.sync bf16 GEMM (unchanged R8 winner, fused-front removed).
// ---------------------------------------------------------------------------
#define X_ROWS   514
#define X_STRIDE 144
#define SM_XHI   0
#define SM_XLO   (X_ROWS * X_STRIDE)
#define SM_WHI   (2 * X_ROWS * X_STRIDE)
#define SM_WLO   (SM_WHI + 64 * 528)
#define SM_F     (SM_WLO + 64 * 528)
#define SMEM_BYTES (SM_F + 256 * 4)

template <bool HAS_LN>
__global__ void __launch_bounds__(512, 1)
mma_stage(const __nv_bfloat16* __restrict__ inhi, const __nv_bfloat16* __restrict__ inlo,
          float* __restrict__ outf,
          __nv_bfloat16* __restrict__ outhi, __nv_bfloat16* __restrict__ outlo,
          const __nv_bfloat16* __restrict__ whi_g, const __nv_bfloat16* __restrict__ wlo_g,
          const float* __restrict__ bias, const float* __restrict__ lng,
          const float* __restrict__ lnb,
          int Lin, int Lout, int numTiles) {
    extern __shared__ char smem[];
    int tid = threadIdx.x, lane = tid & 31, wid = tid >> 5;

    {
        const uint4* s0 = (const uint4*)whi_g;
        const uint4* s1 = (const uint4*)wlo_g;
        uint4* d0 = (uint4*)(smem + SM_WHI);
        uint4* d1 = (uint4*)(smem + SM_WLO);
        for (int i = tid; i < 2112; i += 512) { d0[i] = s0[i]; d1[i] = s1[i]; }
    }
    float* fm   = (float*)(smem + SM_F);
    float* bsm  = fm;
    float* gsm  = fm + 64;
    float* lbsm = fm + 128;
    if (tid < 64) {
        bsm[tid] = bias[tid];
        if (HAS_LN) { gsm[tid] = lng[tid]; lbsm[tid] = lnb[tid]; }
    }
    __syncthreads();

    int warp_p0 = wid * 16;
    int arow   = lane & 15;
    int row2   = 2 * (warp_p0 + arow);
    int acib   = (lane >> 4) << 4;
    int wrow   = (lane & 7) + ((lane >> 4) << 3);
    uint32_t wbyte = (uint32_t)(wrow * 528 + (((lane >> 3) & 1) << 4));
    uint32_t xhi_b = smem_u32(smem + SM_XHI);
    uint32_t xlo_b = smem_u32(smem + SM_XLO);
    uint32_t whi_b = smem_u32(smem + SM_WHI) + wbyte;
    uint32_t wlo_b = smem_u32(smem + SM_WLO) + wbyte;

    int tilesPerB = Lout >> 8;
    for (int tile = blockIdx.x; tile < numTiles; tile += gridDim.x) {
        int b = tile / tilesPerB;
        int t = tile - b * tilesPerB;
        int p0 = t << 8;
        int g0 = 2 * p0 - 1;

        __syncthreads();
        {
            const __nv_bfloat16* ihb = inhi + (size_t)b * Lin * ND;
            const __nv_bfloat16* ilb = inlo + (size_t)b * Lin * ND;
            const uint4 z4 = make_uint4(0u, 0u, 0u, 0u);
            for (int i = tid; i < X_ROWS * 8; i += 512) {
                int row = i >> 3;
                int cb  = (i & 7) << 3;
                int gg  = g0 + row;
                uint4 vh = z4, vl = z4;
                if (gg >= 0 && gg < Lin) {
                    size_t go = (size_t)gg * ND + cb;
                    vh = *(const uint4*)(ihb + go);
                    vl = *(const uint4*)(ilb + go);
                }
                uint32_t xo = (uint32_t)(row * X_STRIDE) + (uint32_t)((cb * 2) ^ ((row & 8) << 1));
                *(uint4*)(smem + SM_XHI + xo) = vh;
                *(uint4*)(smem + SM_XLO + xo) = vl;
            }
        }
        __syncthreads();

        float c[8][4];
#pragma unroll
        for (int n = 0; n < 8; ++n)
#pragma unroll
            for (int q = 0; q < 4; ++q) c[n][q] = 0.f;

#pragma unroll 2
        for (int ks = 0; ks < 16; ++ks) {
            int kk = ks >> 2;
            int xr = row2 + kk;
            uint32_t axo = (uint32_t)(xr * X_STRIDE) +
                           (uint32_t)((((ks & 3) << 5) + acib) ^ ((xr & 8) << 1));
            uint32_t ah[4], al[4], bh[16], bl[16];
            ldsm4(ah, xhi_b + axo);
            ldsm4(al, xlo_b + axo);
            uint32_t wko = (uint32_t)(ks << 5);
            ldsm4(bh + 0,  whi_b + wko);
            ldsm4(bh + 4,  whi_b + wko + 16 * 528);
            ldsm4(bh + 8,  whi_b + wko + 32 * 528);
            ldsm4(bh + 12, whi_b + wko + 48 * 528);
            ldsm4(bl + 0,  wlo_b + wko);
            ldsm4(bl + 4,  wlo_b + wko + 16 * 528);
            ldsm4(bl + 8,  wlo_b + wko + 32 * 528);
            ldsm4(bl + 12, wlo_b + wko + 48 * 528);
#pragma unroll
            for (int g = 0; g < 4; ++g) {
                mma16816(c[2 * g],     ah, bh + 4 * g);
                mma16816(c[2 * g + 1], ah, bh + 4 * g + 2);
                mma16816(c[2 * g],     al, bh + 4 * g);
                mma16816(c[2 * g + 1], al, bh + 4 * g + 2);
                mma16816(c[2 * g],     ah, bl + 4 * g);
                mma16816(c[2 * g + 1], ah, bl + 4 * g + 2);
            }
        }

        int r0 = warp_p0 + (lane >> 2);
        int colb = (lane & 3) * 2;
        float va[16], vb[16];
#pragma unroll
        for (int n = 0; n < 8; ++n) {
            int cn = n * 8 + colb;
            va[2 * n]     = tanhf(c[n][0] + bsm[cn]);
            va[2 * n + 1] = tanhf(c[n][1] + bsm[cn + 1]);
            vb[2 * n]     = tanhf(c[n][2] + bsm[cn]);
            vb[2 * n + 1] = tanhf(c[n][3] + bsm[cn + 1]);
        }
        if (HAS_LN) {
            float s1a = 0.f, s2a = 0.f, s1b = 0.f, s2b = 0.f;
#pragma unroll
            for (int q = 0; q < 16; ++q) {
                s1a += va[q]; s2a += va[q] * va[q];
                s1b += vb[q]; s2b += vb[q] * vb[q];
            }
#pragma unroll
            for (int o = 1; o < 4; o <<= 1) {
                s1a += __shfl_xor_sync(0xffffffffu, s1a, o);
                s2a += __shfl_xor_sync(0xffffffffu, s2a, o);
                s1b += __shfl_xor_sync(0xffffffffu, s1b, o);
                s2b += __shfl_xor_sync(0xffffffffu, s2b, o);
            }
            float ma = s1a * (1.f / 64.f), mb = s1b * (1.f / 64.f);
            float ia = 1.f / sqrtf(s2a * (1.f / 64.f) - ma * ma + 1e-5f);
            float ib = 1.f / sqrtf(s2b * (1.f / 64.f) - mb * mb + 1e-5f);
            size_t rowa = (size_t)b * Lout + p0 + r0;
            __nv_bfloat16* oha = outhi + rowa * ND + colb;
            __nv_bfloat16* ola = outlo + rowa * ND + colb;
            __nv_bfloat16* ohb = oha + 8 * ND;
            __nv_bfloat16* olb = ola + 8 * ND;
#pragma unroll
            for (int n = 0; n < 8; ++n) {
                int cn = n * 8 + colb;
                float a0 = (va[2 * n]     - ma) * ia * gsm[cn]     + lbsm[cn];
                float a1 = (va[2 * n + 1] - ma) * ia * gsm[cn + 1] + lbsm[cn + 1];
                float b0 = (vb[2 * n]     - mb) * ib * gsm[cn]     + lbsm[cn];
                float b1 = (vb[2 * n + 1] - mb) * ib * gsm[cn + 1] + lbsm[cn + 1];
                __nv_bfloat16 h0 = __float2bfloat16(a0);
                __nv_bfloat16 h1 = __float2bfloat16(a1);
                __nv_bfloat16 h2 = __float2bfloat16(b0);
                __nv_bfloat16 h3 = __float2bfloat16(b1);
                *(__nv_bfloat162*)(oha + n * 8) = __nv_bfloat162(h0, h1);
                *(__nv_bfloat162*)(ohb + n * 8) = __nv_bfloat162(h2, h3);
                *(__nv_bfloat162*)(ola + n * 8) = __nv_bfloat162(
                    __float2bfloat16(a0 - __bfloat162float(h0)),
                    __float2bfloat16(a1 - __bfloat162float(h1)));
                *(__nv_bfloat162*)(olb + n * 8) = __nv_bfloat162(
                    __float2bfloat16(b0 - __bfloat162float(h2)),
                    __float2bfloat16(b1 - __bfloat162float(h3)));
            }
        } else {
            float* oa = outf + ((size_t)b * Lout + p0 + r0) * ND + colb;
            float* ob = oa + 8 * ND;
#pragma unroll
            for (int n = 0; n < 8; ++n) {
                *(float2*)(oa + n * 8) = make_float2(va[2 * n], va[2 * n + 1]);
                *(float2*)(ob + n * 8) = make_float2(vb[2 * n], vb[2 * n + 1]);
            }
        }
    }
}

extern "C" void kernel_launch(void* const* d_in, const int* in_sizes, int n_in,
                              void* d_out, int out_size) {
    const float* x   = (const float*)d_in[0];
    const float* tw3 = (const float*)d_in[1];
    const float* tb3 = (const float*)d_in[2];
    const float* tw5 = (const float*)d_in[3];
    const float* tb5 = (const float*)d_in[4];
    const float* tw7 = (const float*)d_in[5];
    const float* tb7 = (const float*)d_in[6];
    const float* tw9 = (const float*)d_in[7];
    const float* tb9 = (const float*)d_in[8];
    const float* cw1 = (const float*)d_in[9];
    const float* cb1 = (const float*)d_in[10];
    const float* cw2 = (const float*)d_in[11];
    const float* cb2 = (const float*)d_in[12];
    const float* cw3 = (const float*)d_in[13];
    const float* cb3 = (const float*)d_in[14];
    const float* lg1 = (const float*)d_in[15];
    const float* lb1 = (const float*)d_in[16];
    const float* lg2 = (const float*)d_in[17];
    const float* lb2 = (const float*)d_in[18];
    (void)in_sizes; (void)n_in; (void)out_size;

    void *wt_p, *h1_p, *h2_p;
    cudaGetSymbolAddress(&wt_p, g_wtb);
    cudaGetSymbolAddress(&h1_p, g_h1b);
    cudaGetSymbolAddress(&h2_p, g_h2b);
    __nv_bfloat16* wtb = (__nv_bfloat16*)wt_p;   // [3][2][64*264]
    __nv_bfloat16* h1hi = (__nv_bfloat16*)h1_p;
    __nv_bfloat16* h1lo = h1hi + (size_t)NB * NL1 * ND;
    __nv_bfloat16* h2hi = (__nv_bfloat16*)h2_p;
    __nv_bfloat16* h2lo = h2hi + (size_t)NB * NL2 * ND;

    cudaFuncSetAttribute((const void*)mma_stage<true>,
                         cudaFuncAttributeMaxDynamicSharedMemorySize, SMEM_BYTES);
    cudaFuncSetAttribute((const void*)mma_stage<false>,
                         cudaFuncAttributeMaxDynamicSharedMemorySize, SMEM_BYTES);
    const int TT_SMEM = (16384 + 34 * 64) * 4;   // 74,240 B
    cudaFuncSetAttribute((const void*)tt_kernel,
                         cudaFuncAttributeMaxDynamicSharedMemorySize, TT_SMEM);

    pe_kernel<<<(NL0 * 32 + 255) / 256, 256>>>();
    wt_kernel<<<(2 * 64 * 64 * 4 + 255) / 256, 256>>>(cw2, cw3);
    w1t_kernel<<<64, 256>>>(cw1);
    weff_kernel<<<10, 256>>>(cw1, tw3, tb3, tw5, tb5, tw7, tb7, tw9, tb9);
    tt_kernel<<<128, 256, TT_SMEM>>>(cb1);

    // stage1: composed 12-tap conv + TT table -> tanh -> LN -> bf16 planes
    dim3 fg(NL1 / 256, NB);
    front_kernel<<<fg, 512>>>(x, h1hi, h1lo, lg1, lb1);

    const int PL = 64 * 264;   // bf16 elements per W plane
    mma_stage<true><<<148, 512, SMEM_BYTES>>>(
        h1hi, h1lo, nullptr, h2hi, h2lo,
        wtb + 1 * 2 * PL, wtb + (1 * 2 + 1) * PL, cb2, lg2, lb2,
        NL1, NL2, NB * (NL2 / 256));
    mma_stage<false><<<148, 512, SMEM_BYTES>>>(
        h2hi, h2lo, (float*)d_out, nullptr, nullptr,
        wtb + 2 * 2 * PL, wtb + (2 * 2 + 1) * PL, cb3, nullptr, nullptr,
        NL2, NL3, NB * (NL3 / 256));
}

// round 13
// speedup vs baseline: 1.3536x; 1.3536x over previous
#include <cuda_runtime.h>
#include <cuda_bf16.h>
#include <math.h>
#include <stdint.h>

#define NB 128
#define ND 64
#define NL0 4096
#define NL1 2048
#define NL2 1024
#define NL3 512

// Scratch (static device allocations allowed; cudaMalloc is not)
__device__ float g_pe[NL0 * ND];                          // 1 MB positional table
__device__ float g_w1t[256 * 64];                         // W1 transposed [k=kk*64+ci][co]
__device__ float g_weff[3][64][12];                       // composed 12-tap conv weights (3 edge cases)
__device__ float g_tbp[4][64];                            // per-kk token-bias projection through W1
__device__ float g_tt[NL1 * 64];                          // TT[p][co] = W1*pe + W1*tb + b1 (case-aware)
__device__ __nv_bfloat16 g_wtb[3][2][64 * 264];           // W hi/lo planes, row stride 264 bf16 (528B)
__device__ __nv_bfloat16 g_h1b[2][(size_t)NB * NL1 * ND]; // h1 as bf16 hi/lo planes
__device__ __nv_bfloat16 g_h2b[2][(size_t)NB * NL2 * ND]; // h2 as bf16 hi/lo planes

__device__ __forceinline__ uint32_t smem_u32(const void* p) {
    uint32_t a;
    asm("{ .reg .u64 t; cvta.to.shared.u64 t, %1; cvt.u32.u64 %0, t; }" : "=r"(a) : "l"(p));
    return a;
}
__device__ __forceinline__ void ldsm4(uint32_t* r, uint32_t a) {
    asm volatile("ldmatrix.sync.aligned.m8n8.x4.shared.b16 {%0,%1,%2,%3}, [%4];"
                 : "=r"(r[0]), "=r"(r[1]), "=r"(r[2]), "=r"(r[3]) : "r"(a));
}
__device__ __forceinline__ void mma16816(float* c, const uint32_t* a, const uint32_t* b) {
    asm volatile("mma.sync.aligned.m16n8k16.row.col.f32.bf16.bf16.f32 "
                 "{%0,%1,%2,%3}, {%4,%5,%6,%7}, {%8,%9}, {%0,%1,%2,%3};"
                 : "+f"(c[0]), "+f"(c[1]), "+f"(c[2]), "+f"(c[3])
                 : "r"(a[0]), "r"(a[1]), "r"(a[2]), "r"(a[3]), "r"(b[0]), "r"(b[1]));
}

// ---------------------------------------------------------------------------
// Fused prep: PE table (double-precision, matches reference fp32 rounding),
// stage2/3 weight split to bf16 hi/lo planes, W1 transpose. Index-partitioned.
// ---------------------------------------------------------------------------
__global__ void prep_kernel(const float* __restrict__ w1,
                            const float* __restrict__ w2,
                            const float* __restrict__ w3) {
    int idx = blockIdx.x * blockDim.x + threadIdx.x;
    if (idx < NL0 * 32) {
        int l = idx >> 5, i = idx & 31;
        float argf = (float)(2 * i) * (float)(-log(10000.0) / 64.0);
        float divf = (float)exp((double)argf);
        float angf = (float)l * divf;
        double ang = (double)angf;
        g_pe[l * ND + 2 * i]     = (float)sin(ang);
        g_pe[l * ND + 2 * i + 1] = (float)cos(ang);
    } else if (idx < NL0 * 32 + 32768) {
        int r = idx - NL0 * 32;
        int s = r >> 14;                      // 0 -> stage2, 1 -> stage3
        int rem = r & 16383;                  // co*256 + ci*4 + kk
        int co = rem >> 8;
        int ci = (rem >> 2) & 63;
        int kk = rem & 3;
        const float* w = (s == 0) ? w2 : w3;
        float v = w[rem];
        __nv_bfloat16 hi = __float2bfloat16(v);
        __nv_bfloat16 lo = __float2bfloat16(v - __bfloat162float(hi));
        int off = co * 264 + kk * 64 + ci;
        g_wtb[s + 1][0][off] = hi;
        g_wtb[s + 1][1][off] = lo;
    } else if (idx < NL0 * 32 + 32768 + 16384) {
        int r = idx - NL0 * 32 - 32768;
        int co = r >> 8;
        int ci = (r >> 2) & 63;
        int kk = r & 3;
        g_w1t[(kk * 64 + ci) * 64 + co] = w1[r];
    }
}

// ---------------------------------------------------------------------------
// Composed front weights (single block, smem-staged w1 + token weights):
//   Weff[case][co][tau] = sum_{kk valid(case), ci, t = tau-4-kk+pad_ci in range}
//                         W1[co,ci,kk] * tokw_ci[t]
// cases: 0 interior, 1 p==0 (kk=0 dropped), 2 p==L-1 (kk=3 dropped).
// g_tbp[kk][co] = sum_ci W1[co,ci,kk] * tok_bias[ci].
// ---------------------------------------------------------------------------
__global__ void weff_kernel(const float* __restrict__ w1,
                            const float* __restrict__ tw3, const float* __restrict__ tb3,
                            const float* __restrict__ tw5, const float* __restrict__ tb5,
                            const float* __restrict__ tw7, const float* __restrict__ tb7,
                            const float* __restrict__ tw9, const float* __restrict__ tb9) {
    extern __shared__ float sm[];
    float* w1s = sm;            // 16384
    float* tws = sm + 16384;    // 384
    float* tbs = sm + 16768;    // 64
    int tid = threadIdx.x;      // 1024 threads
    for (int i = tid; i < 16384; i += 1024) w1s[i] = w1[i];
    if (tid < 48)  tws[tid]       = tw3[tid];
    if (tid < 80)  tws[48 + tid]  = tw5[tid];
    if (tid < 112) tws[128 + tid] = tw7[tid];
    if (tid < 144) tws[240 + tid] = tw9[tid];
    if (tid < 16) {
        tbs[tid]      = tb3[tid];
        tbs[16 + tid] = tb5[tid];
        tbs[32 + tid] = tb7[tid];
        tbs[48 + tid] = tb9[tid];
    }
    __syncthreads();
    for (int idx = tid; idx < 2560; idx += 1024) {
        if (idx < 2304) {
            int cse = idx / 768;
            int rem = idx - cse * 768;
            int co = rem / 12, tau = rem - co * 12;
            float acc = 0.f;
            for (int kk = 0; kk < 4; ++kk) {
                if (cse == 1 && kk == 0) continue;
                if (cse == 2 && kk == 3) continue;
                for (int ci = 0; ci < 64; ++ci) {
                    int g = ci & 3, j = ci >> 2;
                    int pad = g + 1, ks = 3 + 2 * g;
                    int t = tau - 4 - kk + pad;
                    if (t < 0 || t >= ks) continue;
                    int two = (g == 0) ? 0 : (g == 1) ? 48 : (g == 2) ? 128 : 240;
                    acc += w1s[co * 256 + ci * 4 + kk] * tws[two + j * ks + t];
                }
            }
            g_weff[cse][co][tau] = acc;
        } else {
            int r = idx - 2304;
            int kk = r >> 6, co = r & 63;
            float acc = 0.f;
            for (int ci = 0; ci < 64; ++ci)
                acc += w1s[co * 256 + ci * 4 + kk] * tbs[(ci & 3) * 16 + (ci >> 2)];
            g_tbp[kk][co] = acc;
        }
    }
}

// ---------------------------------------------------------------------------
// TT[p][co] = b1[co] + sum_{kk valid} ( tbp[kk][co] + sum_ci W1[co,ci,kk]*pe[2p-1+kk][ci] )
// 128 blocks x 256 threads; block covers 16 positions. W1T + pe rows in smem.
// ---------------------------------------------------------------------------
__global__ void tt_kernel(const float* __restrict__ cb1) {
    extern __shared__ float sm[];
    float* w1ts = sm;              // 16384
    float* pes  = sm + 16384;      // 34*64
    int tid = threadIdx.x;
    int p0 = blockIdx.x * 16;
    for (int i = tid; i < 16384; i += 256) w1ts[i] = g_w1t[i];
    for (int i = tid; i < 34 * 64; i += 256) {
        int r = i >> 6, ci = i & 63;
        int g = 2 * p0 - 1 + r;
        pes[i] = (g >= 0 && g < NL0) ? g_pe[g * 64 + ci] : 0.f;
    }
    __syncthreads();
    int co = tid & 63, py = tid >> 6;
    float acc[4] = {0.f, 0.f, 0.f, 0.f};
    for (int kk = 0; kk < 4; ++kk) {
#pragma unroll 8
        for (int ci = 0; ci < 64; ++ci) {
            float w = w1ts[(kk * 64 + ci) * 64 + co];
#pragma unroll
            for (int i = 0; i < 4; ++i)
                acc[i] += w * pes[(2 * (py * 4 + i) + kk) * 64 + ci];
        }
    }
    float tsum = g_tbp[0][co] + g_tbp[1][co] + g_tbp[2][co] + g_tbp[3][co];
    float bb = cb1[co];
#pragma unroll
    for (int i = 0; i < 4; ++i) {
        int p = p0 + py * 4 + i;
        float bias = bb + tsum;
        if (p == 0)       bias -= g_tbp[0][co];
        if (p == NL1 - 1) bias -= g_tbp[3][co];
        g_tt[p * 64 + co] = acc[i] + bias;
    }
}

// ---------------------------------------------------------------------------
// Stage1 "front": out1[p][co] = tanh( conv12(Weff, x)[p][co] + TT[p][co] ), LN,
// written as bf16 hi/lo planes. 256 threads (reg cap 255 -> NO SPILL), tile =
// 128 positions; thread = 4 co x 8 pos; LN via shfl over the 16-lane group.
// Grid (16, NB).
// ---------------------------------------------------------------------------
__global__ void __launch_bounds__(256)
front_kernel(const float* __restrict__ x,
             __nv_bfloat16* __restrict__ outhi, __nv_bfloat16* __restrict__ outlo,
             const float* __restrict__ lng, const float* __restrict__ lnb) {
    __shared__ float xs[266];
    __shared__ float wsm[768];
    __shared__ float gsm[64], lbsm[64];
    int tid = threadIdx.x;
    int t = blockIdx.x, b = blockIdx.y;
    int p0 = t * 128;
    if (tid < 64) { gsm[tid] = lng[tid]; lbsm[tid] = lnb[tid]; }
    for (int i = tid; i < 768; i += 256) wsm[i] = ((const float*)g_weff)[i]; // case 0
    const float* xb = x + (size_t)b * NL0;
    int base = 2 * p0 - 5;
    for (int i = tid; i < 266; i += 256) {
        int gi = base + i;
        xs[i] = (gi >= 0 && gi < NL0) ? xb[gi] : 0.f;
    }
    __syncthreads();

    int tx = tid & 15, ty = tid >> 4;
    int co0 = tx * 4;
    float wr[4][12];
#pragma unroll
    for (int c = 0; c < 4; ++c)
#pragma unroll
        for (int tau = 0; tau < 12; ++tau) wr[c][tau] = wsm[(co0 + c) * 12 + tau];
    float xr[26];
#pragma unroll
    for (int i = 0; i < 26; ++i) xr[i] = xs[16 * ty + i];

    float acc[8][4];
#pragma unroll
    for (int j = 0; j < 8; ++j) {
#pragma unroll
        for (int c = 0; c < 4; ++c) acc[j][c] = 0.f;
#pragma unroll
        for (int tau = 0; tau < 12; ++tau) {
            float xv = xr[2 * j + tau];
#pragma unroll
            for (int c = 0; c < 4; ++c) acc[j][c] = fmaf(wr[c][tau], xv, acc[j][c]);
        }
    }
    // edge positions use case-1 / case-2 composed weights
    if (t == 0 && ty == 0) {
#pragma unroll
        for (int c = 0; c < 4; ++c) {
            float a = 0.f;
            for (int tau = 0; tau < 12; ++tau) a = fmaf(g_weff[1][co0 + c][tau], xr[tau], a);
            acc[0][c] = a;
        }
    }
    if (t == 15 && ty == 15) {
#pragma unroll
        for (int c = 0; c < 4; ++c) {
            float a = 0.f;
            for (int tau = 0; tau < 12; ++tau) a = fmaf(g_weff[2][co0 + c][tau], xr[14 + tau], a);
            acc[7][c] = a;
        }
    }

#pragma unroll
    for (int j = 0; j < 8; ++j) {
        int p = p0 + ty * 8 + j;
        float4 tt4 = *(const float4*)(g_tt + p * 64 + co0);
        float v0 = tanhf(acc[j][0] + tt4.x);
        float v1 = tanhf(acc[j][1] + tt4.y);
        float v2 = tanhf(acc[j][2] + tt4.z);
        float v3 = tanhf(acc[j][3] + tt4.w);
        float s1 = v0 + v1 + v2 + v3;
        float s2 = v0 * v0 + v1 * v1 + v2 * v2 + v3 * v3;
#pragma unroll
        for (int o = 1; o < 16; o <<= 1) {
            s1 += __shfl_xor_sync(0xffffffffu, s1, o);
            s2 += __shfl_xor_sync(0xffffffffu, s2, o);
        }
        float m   = s1 * (1.f / 64.f);
        float var = s2 * (1.f / 64.f) - m * m;
        float inv = 1.f / sqrtf(var + 1e-5f);
        float o0 = (v0 - m) * inv * gsm[co0 + 0] + lbsm[co0 + 0];
        float o1 = (v1 - m) * inv * gsm[co0 + 1] + lbsm[co0 + 1];
        float o2 = (v2 - m) * inv * gsm[co0 + 2] + lbsm[co0 + 2];
        float o3 = (v3 - m) * inv * gsm[co0 + 3] + lbsm[co0 + 3];
        size_t ro = ((size_t)b * NL1 + p) * ND + co0;
        __nv_bfloat16 h0 = __float2bfloat16(o0);
        __nv_bfloat16 h1 = __float2bfloat16(o1);
        __nv_bfloat16 h2 = __float2bfloat16(o2);
        __nv_bfloat16 h3 = __float2bfloat16(o3);
        *(__nv_bfloat162*)(outhi + ro)     = __nv_bfloat162(h0, h1);
        *(__nv_bfloat162*)(outhi + ro + 2) = __nv_bfloat162(h2, h3);
        *(__nv_bfloat162*)(outlo + ro)     = __nv_bfloat162(
            __float2bfloat16(o0 - __bfloat162float(h0)),
            __float2bfloat16(o1 - __bfloat162float(h1)));
        *(__nv_bfloat162*)(outlo + ro + 2) = __nv_bfloat162(
            __float2bfloat16(o2 - __bfloat162float(h2)),
            __float2bfloat16(o3 - __bfloat162float(h3)));
    }
}

// ---------------------------------------------------------------------------
// Stages 2/3 as mma.sync bf16 GEMM (unchanged R8 winner).
// ---------------------------------------------------------------------------
#define X_ROWS   514
#define X_STRIDE 144
#define SM_XHI   0
#define SM_XLO   (X_ROWS * X_STRIDE)
#define SM_WHI   (2 * X_ROWS * X_STRIDE)
#define SM_WLO   (SM_WHI + 64 * 528)
#define SM_F     (SM_WLO + 64 * 528)
#define SMEM_BYTES (SM_F + 256 * 4)

template <bool HAS_LN>
__global__ void __launch_bounds__(512, 1)
mma_stage(const __nv_bfloat16* __restrict__ inhi, const __nv_bfloat16* __restrict__ inlo,
          float* __restrict__ outf,
          __nv_bfloat16* __restrict__ outhi, __nv_bfloat16* __restrict__ outlo,
          const __nv_bfloat16* __restrict__ whi_g, const __nv_bfloat16* __restrict__ wlo_g,
          const float* __restrict__ bias, const float* __restrict__ lng,
          const float* __restrict__ lnb,
          int Lin, int Lout, int numTiles) {
    extern __shared__ char smem[];
    int tid = threadIdx.x, lane = tid & 31, wid = tid >> 5;

    {
        const uint4* s0 = (const uint4*)whi_g;
        const uint4* s1 = (const uint4*)wlo_g;
        uint4* d0 = (uint4*)(smem + SM_WHI);
        uint4* d1 = (uint4*)(smem + SM_WLO);
        for (int i = tid; i < 2112; i += 512) { d0[i] = s0[i]; d1[i] = s1[i]; }
    }
    float* fm   = (float*)(smem + SM_F);
    float* bsm  = fm;
    float* gsm  = fm + 64;
    float* lbsm = fm + 128;
    if (tid < 64) {
        bsm[tid] = bias[tid];
        if (HAS_LN) { gsm[tid] = lng[tid]; lbsm[tid] = lnb[tid]; }
    }
    __syncthreads();

    int warp_p0 = wid * 16;
    int arow   = lane & 15;
    int row2   = 2 * (warp_p0 + arow);
    int acib   = (lane >> 4) << 4;
    int wrow   = (lane & 7) + ((lane >> 4) << 3);
    uint32_t wbyte = (uint32_t)(wrow * 528 + (((lane >> 3) & 1) << 4));
    uint32_t xhi_b = smem_u32(smem + SM_XHI);
    uint32_t xlo_b = smem_u32(smem + SM_XLO);
    uint32_t whi_b = smem_u32(smem + SM_WHI) + wbyte;
    uint32_t wlo_b = smem_u32(smem + SM_WLO) + wbyte;

    int tilesPerB = Lout >> 8;
    for (int tile = blockIdx.x; tile < numTiles; tile += gridDim.x) {
        int b = tile / tilesPerB;
        int t = tile - b * tilesPerB;
        int p0 = t << 8;
        int g0 = 2 * p0 - 1;

        __syncthreads();
        {
            const __nv_bfloat16* ihb = inhi + (size_t)b * Lin * ND;
            const __nv_bfloat16* ilb = inlo + (size_t)b * Lin * ND;
            const uint4 z4 = make_uint4(0u, 0u, 0u, 0u);
            for (int i = tid; i < X_ROWS * 8; i += 512) {
                int row = i >> 3;
                int cb  = (i & 7) << 3;
                int gg  = g0 + row;
                uint4 vh = z4, vl = z4;
                if (gg >= 0 && gg < Lin) {
                    size_t go = (size_t)gg * ND + cb;
                    vh = *(const uint4*)(ihb + go);
                    vl = *(const uint4*)(ilb + go);
                }
                uint32_t xo = (uint32_t)(row * X_STRIDE) + (uint32_t)((cb * 2) ^ ((row & 8) << 1));
                *(uint4*)(smem + SM_XHI + xo) = vh;
                *(uint4*)(smem + SM_XLO + xo) = vl;
            }
        }
        __syncthreads();

        float c[8][4];
#pragma unroll
        for (int n = 0; n < 8; ++n)
#pragma unroll
            for (int q = 0; q < 4; ++q) c[n][q] = 0.f;

#pragma unroll 2
        for (int ks = 0; ks < 16; ++ks) {
            int kk = ks >> 2;
            int xr = row2 + kk;
            uint32_t axo = (uint32_t)(xr * X_STRIDE) +
                           (uint32_t)((((ks & 3) << 5) + acib) ^ ((xr & 8) << 1));
            uint32_t ah[4], al[4], bh[16], bl[16];
            ldsm4(ah, xhi_b + axo);
            ldsm4(al, xlo_b + axo);
            uint32_t wko = (uint32_t)(ks << 5);
            ldsm4(bh + 0,  whi_b + wko);
            ldsm4(bh + 4,  whi_b + wko + 16 * 528);
            ldsm4(bh + 8,  whi_b + wko + 32 * 528);
            ldsm4(bh + 12, whi_b + wko + 48 * 528);
            ldsm4(bl + 0,  wlo_b + wko);
            ldsm4(bl + 4,  wlo_b + wko + 16 * 528);
            ldsm4(bl + 8,  wlo_b + wko + 32 * 528);
            ldsm4(bl + 12, wlo_b + wko + 48 * 528);
#pragma unroll
            for (int g = 0; g < 4; ++g) {
                mma16816(c[2 * g],     ah, bh + 4 * g);
                mma16816(c[2 * g + 1], ah, bh + 4 * g + 2);
                mma16816(c[2 * g],     al, bh + 4 * g);
                mma16816(c[2 * g + 1], al, bh + 4 * g + 2);
                mma16816(c[2 * g],     ah, bl + 4 * g);
                mma16816(c[2 * g + 1], ah, bl + 4 * g + 2);
            }
        }

        int r0 = warp_p0 + (lane >> 2);
        int colb = (lane & 3) * 2;
        float va[16], vb[16];
#pragma unroll
        for (int n = 0; n < 8; ++n) {
            int cn = n * 8 + colb;
            va[2 * n]     = tanhf(c[n][0] + bsm[cn]);
            va[2 * n + 1] = tanhf(c[n][1] + bsm[cn + 1]);
            vb[2 * n]     = tanhf(c[n][2] + bsm[cn]);
            vb[2 * n + 1] = tanhf(c[n][3] + bsm[cn + 1]);
        }
        if (HAS_LN) {
            float s1a = 0.f, s2a = 0.f, s1b = 0.f, s2b = 0.f;
#pragma unroll
            for (int q = 0; q < 16; ++q) {
                s1a += va[q]; s2a += va[q] * va[q];
                s1b += vb[q]; s2b += vb[q] * vb[q];
            }
#pragma unroll
            for (int o = 1; o < 4; o <<= 1) {
                s1a += __shfl_xor_sync(0xffffffffu, s1a, o);
                s2a += __shfl_xor_sync(0xffffffffu, s2a, o);
                s1b += __shfl_xor_sync(0xffffffffu, s1b, o);
                s2b += __shfl_xor_sync(0xffffffffu, s2b, o);
            }
            float ma = s1a * (1.f / 64.f), mb = s1b * (1.f / 64.f);
            float ia = 1.f / sqrtf(s2a * (1.f / 64.f) - ma * ma + 1e-5f);
            float ib = 1.f / sqrtf(s2b * (1.f / 64.f) - mb * mb + 1e-5f);
            size_t rowa = (size_t)b * Lout + p0 + r0;
            __nv_bfloat16* oha = outhi + rowa * ND + colb;
            __nv_bfloat16* ola = outlo + rowa * ND + colb;
            __nv_bfloat16* ohb = oha + 8 * ND;
            __nv_bfloat16* olb = ola + 8 * ND;
#pragma unroll
            for (int n = 0; n < 8; ++n) {
                int cn = n * 8 + colb;
                float a0 = (va[2 * n]     - ma) * ia * gsm[cn]     + lbsm[cn];
                float a1 = (va[2 * n + 1] - ma) * ia * gsm[cn + 1] + lbsm[cn + 1];
                float b0 = (vb[2 * n]     - mb) * ib * gsm[cn]     + lbsm[cn];
                float b1 = (vb[2 * n + 1] - mb) * ib * gsm[cn + 1] + lbsm[cn + 1];
                __nv_bfloat16 h0 = __float2bfloat16(a0);
                __nv_bfloat16 h1 = __float2bfloat16(a1);
                __nv_bfloat16 h2 = __float2bfloat16(b0);
                __nv_bfloat16 h3 = __float2bfloat16(b1);
                *(__nv_bfloat162*)(oha + n * 8) = __nv_bfloat162(h0, h1);
                *(__nv_bfloat162*)(ohb + n * 8) = __nv_bfloat162(h2, h3);
                *(__nv_bfloat162*)(ola + n * 8) = __nv_bfloat162(
                    __float2bfloat16(a0 - __bfloat162float(h0)),
                    __float2bfloat16(a1 - __bfloat162float(h1)));
                *(__nv_bfloat162*)(olb + n * 8) = __nv_bfloat162(
                    __float2bfloat16(b0 - __bfloat162float(h2)),
                    __float2bfloat16(b1 - __bfloat162float(h3)));
            }
        } else {
            float* oa = outf + ((size_t)b * Lout + p0 + r0) * ND + colb;
            float* ob = oa + 8 * ND;
#pragma unroll
            for (int n = 0; n < 8; ++n) {
                *(float2*)(oa + n * 8) = make_float2(va[2 * n], va[2 * n + 1]);
                *(float2*)(ob + n * 8) = make_float2(vb[2 * n], vb[2 * n + 1]);
            }
        }
    }
}

extern "C" void kernel_launch(void* const* d_in, const int* in_sizes, int n_in,
                              void* d_out, int out_size) {
    const float* x   = (const float*)d_in[0];
    const float* tw3 = (const float*)d_in[1];
    const float* tb3 = (const float*)d_in[2];
    const float* tw5 = (const float*)d_in[3];
    const float* tb5 = (const float*)d_in[4];
    const float* tw7 = (const float*)d_in[5];
    const float* tb7 = (const float*)d_in[6];
    const float* tw9 = (const float*)d_in[7];
    const float* tb9 = (const float*)d_in[8];
    const float* cw1 = (const float*)d_in[9];
    const float* cb1 = (const float*)d_in[10];
    const float* cw2 = (const float*)d_in[11];
    const float* cb2 = (const float*)d_in[12];
    const float* cw3 = (const float*)d_in[13];
    const float* cb3 = (const float*)d_in[14];
    const float* lg1 = (const float*)d_in[15];
    const float* lb1 = (const float*)d_in[16];
    const float* lg2 = (const float*)d_in[17];
    const float* lb2 = (const float*)d_in[18];
    (void)in_sizes; (void)n_in; (void)out_size;

    void *wt_p, *h1_p, *h2_p;
    cudaGetSymbolAddress(&wt_p, g_wtb);
    cudaGetSymbolAddress(&h1_p, g_h1b);
    cudaGetSymbolAddress(&h2_p, g_h2b);
    __nv_bfloat16* wtb = (__nv_bfloat16*)wt_p;   // [3][2][64*264]
    __nv_bfloat16* h1hi = (__nv_bfloat16*)h1_p;
    __nv_bfloat16* h1lo = h1hi + (size_t)NB * NL1 * ND;
    __nv_bfloat16* h2hi = (__nv_bfloat16*)h2_p;
    __nv_bfloat16* h2lo = h2hi + (size_t)NB * NL2 * ND;

    cudaFuncSetAttribute((const void*)mma_stage<true>,
                         cudaFuncAttributeMaxDynamicSharedMemorySize, SMEM_BYTES);
    cudaFuncSetAttribute((const void*)mma_stage<false>,
                         cudaFuncAttributeMaxDynamicSharedMemorySize, SMEM_BYTES);
    const int TT_SMEM = (16384 + 34 * 64) * 4;        // 74,240 B
    cudaFuncSetAttribute((const void*)tt_kernel,
                         cudaFuncAttributeMaxDynamicSharedMemorySize, TT_SMEM);
    const int WEFF_SMEM = (16384 + 384 + 64) * 4;     // 67,328 B
    cudaFuncSetAttribute((const void*)weff_kernel,
                         cudaFuncAttributeMaxDynamicSharedMemorySize, WEFF_SMEM);

    const int PREP_N = NL0 * 32 + 32768 + 16384;
    prep_kernel<<<(PREP_N + 255) / 256, 256>>>(cw1, cw2, cw3);
    weff_kernel<<<1, 1024, WEFF_SMEM>>>(cw1, tw3, tb3, tw5, tb5, tw7, tb7, tw9, tb9);
    tt_kernel<<<128, 256, TT_SMEM>>>(cb1);

    // stage1: composed 12-tap conv + TT table -> tanh -> LN -> bf16 planes
    dim3 fg(NL1 / 128, NB);
    front_kernel<<<fg, 256>>>(x, h1hi, h1lo, lg1, lb1);

    const int PL = 64 * 264;   // bf16 elements per W plane
    mma_stage<true><<<148, 512, SMEM_BYTES>>>(
        h1hi, h1lo, nullptr, h2hi, h2lo,
        wtb + 1 * 2 * PL, wtb + (1 * 2 + 1) * PL, cb2, lg2, lb2,
        NL1, NL2, NB * (NL2 / 256));
    mma_stage<false><<<148, 512, SMEM_BYTES>>>(
        h2hi, h2lo, (float*)d_out, nullptr, nullptr,
        wtb + 2 * 2 * PL, wtb + (2 * 2 + 1) * PL, cb3, nullptr, nullptr,
        NL2, NL3, NB * (NL3 / 256));
}

// round 15
// speedup vs baseline: 1.4802x; 1.0936x over previous
#include <cuda_runtime.h>
#include <cuda_bf16.h>
#include <math.h>
#include <stdint.h>

#define NB 128
#define ND 64
#define NL0 4096
#define NL1 2048
#define NL2 1024
#define NL3 512

// Scratch (static device allocations allowed; cudaMalloc is not)
__device__ float g_pe[NL0 * ND];                          // 1 MB positional table
__device__ float g_w1t[256 * 64];                         // W1 transposed [k=kk*64+ci][co]
__device__ float g_weff[3][64][12];                       // composed 12-tap conv weights (3 edge cases)
__device__ float g_tbp[4][64];                            // per-kk token-bias projection through W1
__device__ float g_tt[NL1 * 64];                          // TT[p][co] = W1*pe + W1*tb + b1 (case-aware)
__device__ __nv_bfloat16 g_wtb[3][2][64 * 264];           // W hi/lo planes, row stride 264 bf16 (528B)
__device__ __nv_bfloat16 g_h1b[2][(size_t)NB * NL1 * ND]; // h1 as bf16 hi/lo planes
__device__ __nv_bfloat16 g_h2b[2][(size_t)NB * NL2 * ND]; // h2 as bf16 hi/lo planes

__device__ __forceinline__ uint32_t smem_u32(const void* p) {
    uint32_t a;
    asm("{ .reg .u64 t; cvta.to.shared.u64 t, %1; cvt.u32.u64 %0, t; }" : "=r"(a) : "l"(p));
    return a;
}
__device__ __forceinline__ void ldsm4(uint32_t* r, uint32_t a) {
    asm volatile("ldmatrix.sync.aligned.m8n8.x4.shared.b16 {%0,%1,%2,%3}, [%4];"
                 : "=r"(r[0]), "=r"(r[1]), "=r"(r[2]), "=r"(r[3]) : "r"(a));
}
__device__ __forceinline__ void mma16816(float* c, const uint32_t* a, const uint32_t* b) {
    asm volatile("mma.sync.aligned.m16n8k16.row.col.f32.bf16.bf16.f32 "
                 "{%0,%1,%2,%3}, {%4,%5,%6,%7}, {%8,%9}, {%0,%1,%2,%3};"
                 : "+f"(c[0]), "+f"(c[1]), "+f"(c[2]), "+f"(c[3])
                 : "r"(a[0]), "r"(a[1]), "r"(a[2]), "r"(a[3]), "r"(b[0]), "r"(b[1]));
}
// MUFU-based tanh: abs err ~1ulp-of-1 (~6e-8); far under the 1e-3 budget.
__device__ __forceinline__ float fast_tanh(float x) {
    float e = __expf(-2.f * fabsf(x));
    float t = __fdividef(1.f - e, 1.f + e);
    return copysignf(t, x);
}
__device__ __forceinline__ uint32_t pack_bf2(float a, float b) {
    __nv_bfloat162 v(__float2bfloat16(a), __float2bfloat16(b));
    return *(uint32_t*)&v;
}

// ---------------------------------------------------------------------------
// Fused prep: PE table (fp32 trig; sinf/cosf are fully range-reduced, ~2ulp),
// stage2/3 weight split to bf16 hi/lo planes, W1 transpose. Index-partitioned.
// ---------------------------------------------------------------------------
__global__ void prep_kernel(const float* __restrict__ w1,
                            const float* __restrict__ w2,
                            const float* __restrict__ w3) {
    int idx = blockIdx.x * blockDim.x + threadIdx.x;
    if (idx < NL0 * 32) {
        int l = idx >> 5, i = idx & 31;
        float argf = (float)(2 * i) * (float)(-log(10000.0) / 64.0);
        float divf = __expf(argf);
        float ang  = (float)l * divf;
        g_pe[l * ND + 2 * i]     = sinf(ang);
        g_pe[l * ND + 2 * i + 1] = cosf(ang);
    } else if (idx < NL0 * 32 + 32768) {
        int r = idx - NL0 * 32;
        int s = r >> 14;                      // 0 -> stage2, 1 -> stage3
        int rem = r & 16383;                  // co*256 + ci*4 + kk
        int co = rem >> 8;
        int ci = (rem >> 2) & 63;
        int kk = rem & 3;
        const float* w = (s == 0) ? w2 : w3;
        float v = w[rem];
        __nv_bfloat16 hi = __float2bfloat16(v);
        __nv_bfloat16 lo = __float2bfloat16(v - __bfloat162float(hi));
        int off = co * 264 + kk * 64 + ci;
        g_wtb[s + 1][0][off] = hi;
        g_wtb[s + 1][1][off] = lo;
    } else if (idx < NL0 * 32 + 32768 + 16384) {
        int r = idx - NL0 * 32 - 32768;
        int co = r >> 8;
        int ci = (r >> 2) & 63;
        int kk = r & 3;
        g_w1t[(kk * 64 + ci) * 64 + co] = w1[r];
    }
}

// ---------------------------------------------------------------------------
// Composed front weights (single block, smem-staged w1 + token weights).
// ---------------------------------------------------------------------------
__global__ void weff_kernel(const float* __restrict__ w1,
                            const float* __restrict__ tw3, const float* __restrict__ tb3,
                            const float* __restrict__ tw5, const float* __restrict__ tb5,
                            const float* __restrict__ tw7, const float* __restrict__ tb7,
                            const float* __restrict__ tw9, const float* __restrict__ tb9) {
    extern __shared__ float sm[];
    float* w1s = sm;            // 16384
    float* tws = sm + 16384;    // 384
    float* tbs = sm + 16768;    // 64
    int tid = threadIdx.x;      // 1024 threads
    for (int i = tid; i < 16384; i += 1024) w1s[i] = w1[i];
    if (tid < 48)  tws[tid]       = tw3[tid];
    if (tid < 80)  tws[48 + tid]  = tw5[tid];
    if (tid < 112) tws[128 + tid] = tw7[tid];
    if (tid < 144) tws[240 + tid] = tw9[tid];
    if (tid < 16) {
        tbs[tid]      = tb3[tid];
        tbs[16 + tid] = tb5[tid];
        tbs[32 + tid] = tb7[tid];
        tbs[48 + tid] = tb9[tid];
    }
    __syncthreads();
    for (int idx = tid; idx < 2560; idx += 1024) {
        if (idx < 2304) {
            int cse = idx / 768;
            int rem = idx - cse * 768;
            int co = rem / 12, tau = rem - co * 12;
            float acc = 0.f;
            for (int kk = 0; kk < 4; ++kk) {
                if (cse == 1 && kk == 0) continue;
                if (cse == 2 && kk == 3) continue;
                for (int ci = 0; ci < 64; ++ci) {
                    int g = ci & 3, j = ci >> 2;
                    int pad = g + 1, ks = 3 + 2 * g;
                    int t = tau - 4 - kk + pad;
                    if (t < 0 || t >= ks) continue;
                    int two = (g == 0) ? 0 : (g == 1) ? 48 : (g == 2) ? 128 : 240;
                    acc += w1s[co * 256 + ci * 4 + kk] * tws[two + j * ks + t];
                }
            }
            g_weff[cse][co][tau] = acc;
        } else {
            int r = idx - 2304;
            int kk = r >> 6, co = r & 63;
            float acc = 0.f;
            for (int ci = 0; ci < 64; ++ci)
                acc += w1s[co * 256 + ci * 4 + kk] * tbs[(ci & 3) * 16 + (ci >> 2)];
            g_tbp[kk][co] = acc;
        }
    }
}

// ---------------------------------------------------------------------------
// TT[p][co] = b1[co] + sum_{kk valid} ( tbp[kk][co] + sum_ci W1[co,ci,kk]*pe[2p-1+kk][ci] )
// ---------------------------------------------------------------------------
__global__ void tt_kernel(const float* __restrict__ cb1) {
    extern __shared__ float sm[];
    float* w1ts = sm;              // 16384
    float* pes  = sm + 16384;      // 34*64
    int tid = threadIdx.x;
    int p0 = blockIdx.x * 16;
    for (int i = tid; i < 16384; i += 256) w1ts[i] = g_w1t[i];
    for (int i = tid; i < 34 * 64; i += 256) {
        int r = i >> 6, ci = i & 63;
        int g = 2 * p0 - 1 + r;
        pes[i] = (g >= 0 && g < NL0) ? g_pe[g * 64 + ci] : 0.f;
    }
    __syncthreads();
    int co = tid & 63, py = tid >> 6;
    float acc[4] = {0.f, 0.f, 0.f, 0.f};
    for (int kk = 0; kk < 4; ++kk) {
#pragma unroll 8
        for (int ci = 0; ci < 64; ++ci) {
            float w = w1ts[(kk * 64 + ci) * 64 + co];
#pragma unroll
            for (int i = 0; i < 4; ++i)
                acc[i] += w * pes[(2 * (py * 4 + i) + kk) * 64 + ci];
        }
    }
    float tsum = g_tbp[0][co] + g_tbp[1][co] + g_tbp[2][co] + g_tbp[3][co];
    float bb = cb1[co];
#pragma unroll
    for (int i = 0; i < 4; ++i) {
        int p = p0 + py * 4 + i;
        float bias = bb + tsum;
        if (p == 0)       bias -= g_tbp[0][co];
        if (p == NL1 - 1) bias -= g_tbp[3][co];
        g_tt[p * 64 + co] = acc[i] + bias;
    }
}

// ---------------------------------------------------------------------------
// Stage1 "front": out1[p][co] = tanh( conv12(Weff, x)[p][co] + TT[p][co] ), LN,
// written as bf16 hi/lo planes (uint2 stores). 256 threads, tile 128 positions,
// thread = 4 co x 8 pos; LN via shfl over the 16-lane group. Grid (16, NB).
// ---------------------------------------------------------------------------
__global__ void __launch_bounds__(256)
front_kernel(const float* __restrict__ x,
             __nv_bfloat16* __restrict__ outhi, __nv_bfloat16* __restrict__ outlo,
             const float* __restrict__ lng, const float* __restrict__ lnb) {
    __shared__ float xs[266];
    __shared__ float wsm[768];
    __shared__ float gsm[64], lbsm[64];
    int tid = threadIdx.x;
    int t = blockIdx.x, b = blockIdx.y;
    int p0 = t * 128;
    if (tid < 64) { gsm[tid] = lng[tid]; lbsm[tid] = lnb[tid]; }
    for (int i = tid; i < 768; i += 256) wsm[i] = ((const float*)g_weff)[i]; // case 0
    const float* xb = x + (size_t)b * NL0;
    int base = 2 * p0 - 5;
    for (int i = tid; i < 266; i += 256) {
        int gi = base + i;
        xs[i] = (gi >= 0 && gi < NL0) ? xb[gi] : 0.f;
    }
    __syncthreads();

    int tx = tid & 15, ty = tid >> 4;
    int co0 = tx * 4;
    float wr[4][12];
#pragma unroll
    for (int c = 0; c < 4; ++c)
#pragma unroll
        for (int tau = 0; tau < 12; ++tau) wr[c][tau] = wsm[(co0 + c) * 12 + tau];
    float xr[26];
#pragma unroll
    for (int i = 0; i < 26; ++i) xr[i] = xs[16 * ty + i];

    float acc[8][4];
#pragma unroll
    for (int j = 0; j < 8; ++j) {
#pragma unroll
        for (int c = 0; c < 4; ++c) acc[j][c] = 0.f;
#pragma unroll
        for (int tau = 0; tau < 12; ++tau) {
            float xv = xr[2 * j + tau];
#pragma unroll
            for (int c = 0; c < 4; ++c) acc[j][c] = fmaf(wr[c][tau], xv, acc[j][c]);
        }
    }
    // edge positions use case-1 / case-2 composed weights
    if (t == 0 && ty == 0) {
#pragma unroll
        for (int c = 0; c < 4; ++c) {
            float a = 0.f;
            for (int tau = 0; tau < 12; ++tau) a = fmaf(g_weff[1][co0 + c][tau], xr[tau], a);
            acc[0][c] = a;
        }
    }
    if (t == 15 && ty == 15) {
#pragma unroll
        for (int c = 0; c < 4; ++c) {
            float a = 0.f;
            for (int tau = 0; tau < 12; ++tau) a = fmaf(g_weff[2][co0 + c][tau], xr[14 + tau], a);
            acc[7][c] = a;
        }
    }

#pragma unroll
    for (int j = 0; j < 8; ++j) {
        int p = p0 + ty * 8 + j;
        float4 tt4 = *(const float4*)(g_tt + p * 64 + co0);
        float v0 = fast_tanh(acc[j][0] + tt4.x);
        float v1 = fast_tanh(acc[j][1] + tt4.y);
        float v2 = fast_tanh(acc[j][2] + tt4.z);
        float v3 = fast_tanh(acc[j][3] + tt4.w);
        float s1 = v0 + v1 + v2 + v3;
        float s2 = v0 * v0 + v1 * v1 + v2 * v2 + v3 * v3;
#pragma unroll
        for (int o = 1; o < 16; o <<= 1) {
            s1 += __shfl_xor_sync(0xffffffffu, s1, o);
            s2 += __shfl_xor_sync(0xffffffffu, s2, o);
        }
        float m   = s1 * (1.f / 64.f);
        float var = s2 * (1.f / 64.f) - m * m;
        float inv = 1.f / sqrtf(var + 1e-5f);
        float o0 = (v0 - m) * inv * gsm[co0 + 0] + lbsm[co0 + 0];
        float o1 = (v1 - m) * inv * gsm[co0 + 1] + lbsm[co0 + 1];
        float o2 = (v2 - m) * inv * gsm[co0 + 2] + lbsm[co0 + 2];
        float o3 = (v3 - m) * inv * gsm[co0 + 3] + lbsm[co0 + 3];
        size_t ro = ((size_t)b * NL1 + p) * ND + co0;
        __nv_bfloat16 h0 = __float2bfloat16(o0);
        __nv_bfloat16 h1 = __float2bfloat16(o1);
        __nv_bfloat16 h2 = __float2bfloat16(o2);
        __nv_bfloat16 h3 = __float2bfloat16(o3);
        uint32_t hi01, hi23;
        { __nv_bfloat162 v(h0, h1); hi01 = *(uint32_t*)&v; }
        { __nv_bfloat162 v(h2, h3); hi23 = *(uint32_t*)&v; }
        *(uint2*)(outhi + ro) = make_uint2(hi01, hi23);
        uint32_t lo01 = pack_bf2(o0 - __bfloat162float(h0), o1 - __bfloat162float(h1));
        uint32_t lo23 = pack_bf2(o2 - __bfloat162float(h2), o3 - __bfloat162float(h3));
        *(uint2*)(outlo + ro) = make_uint2(lo01, lo23);
    }
}

// ---------------------------------------------------------------------------
// Stages 2/3 as mma.sync bf16 GEMM (R8 mainloop; fast_tanh epilogue).
// ---------------------------------------------------------------------------
#define X_ROWS   514
#define X_STRIDE 144
#define SM_XHI   0
#define SM_XLO   (X_ROWS * X_STRIDE)
#define SM_WHI   (2 * X_ROWS * X_STRIDE)
#define SM_WLO   (SM_WHI + 64 * 528)
#define SM_F     (SM_WLO + 64 * 528)
#define SMEM_BYTES (SM_F + 256 * 4)

template <bool HAS_LN>
__global__ void __launch_bounds__(512, 1)
mma_stage(const __nv_bfloat16* __restrict__ inhi, const __nv_bfloat16* __restrict__ inlo,
          float* __restrict__ outf,
          __nv_bfloat16* __restrict__ outhi, __nv_bfloat16* __restrict__ outlo,
          const __nv_bfloat16* __restrict__ whi_g, const __nv_bfloat16* __restrict__ wlo_g,
          const float* __restrict__ bias, const float* __restrict__ lng,
          const float* __restrict__ lnb,
          int Lin, int Lout, int numTiles) {
    extern __shared__ char smem[];
    int tid = threadIdx.x, lane = tid & 31, wid = tid >> 5;

    {
        const uint4* s0 = (const uint4*)whi_g;
        const uint4* s1 = (const uint4*)wlo_g;
        uint4* d0 = (uint4*)(smem + SM_WHI);
        uint4* d1 = (uint4*)(smem + SM_WLO);
        for (int i = tid; i < 2112; i += 512) { d0[i] = s0[i]; d1[i] = s1[i]; }
    }
    float* fm   = (float*)(smem + SM_F);
    float* bsm  = fm;
    float* gsm  = fm + 64;
    float* lbsm = fm + 128;
    if (tid < 64) {
        bsm[tid] = bias[tid];
        if (HAS_LN) { gsm[tid] = lng[tid]; lbsm[tid] = lnb[tid]; }
    }
    __syncthreads();

    int warp_p0 = wid * 16;
    int arow   = lane & 15;
    int row2   = 2 * (warp_p0 + arow);
    int acib   = (lane >> 4) << 4;
    int wrow   = (lane & 7) + ((lane >> 4) << 3);
    uint32_t wbyte = (uint32_t)(wrow * 528 + (((lane >> 3) & 1) << 4));
    uint32_t xhi_b = smem_u32(smem + SM_XHI);
    uint32_t xlo_b = smem_u32(smem + SM_XLO);
    uint32_t whi_b = smem_u32(smem + SM_WHI) + wbyte;
    uint32_t wlo_b = smem_u32(smem + SM_WLO) + wbyte;

    int tilesPerB = Lout >> 8;
    for (int tile = blockIdx.x; tile < numTiles; tile += gridDim.x) {
        int b = tile / tilesPerB;
        int t = tile - b * tilesPerB;
        int p0 = t << 8;
        int g0 = 2 * p0 - 1;

        __syncthreads();
        {
            const __nv_bfloat16* ihb = inhi + (size_t)b * Lin * ND;
            const __nv_bfloat16* ilb = inlo + (size_t)b * Lin * ND;
            const uint4 z4 = make_uint4(0u, 0u, 0u, 0u);
            for (int i = tid; i < X_ROWS * 8; i += 512) {
                int row = i >> 3;
                int cb  = (i & 7) << 3;
                int gg  = g0 + row;
                uint4 vh = z4, vl = z4;
                if (gg >= 0 && gg < Lin) {
                    size_t go = (size_t)gg * ND + cb;
                    vh = *(const uint4*)(ihb + go);
                    vl = *(const uint4*)(ilb + go);
                }
                uint32_t xo = (uint32_t)(row * X_STRIDE) + (uint32_t)((cb * 2) ^ ((row & 8) << 1));
                *(uint4*)(smem + SM_XHI + xo) = vh;
                *(uint4*)(smem + SM_XLO + xo) = vl;
            }
        }
        __syncthreads();

        float c[8][4];
#pragma unroll
        for (int n = 0; n < 8; ++n)
#pragma unroll
            for (int q = 0; q < 4; ++q) c[n][q] = 0.f;

#pragma unroll 2
        for (int ks = 0; ks < 16; ++ks) {
            int kk = ks >> 2;
            int xr = row2 + kk;
            uint32_t axo = (uint32_t)(xr * X_STRIDE) +
                           (uint32_t)((((ks & 3) << 5) + acib) ^ ((xr & 8) << 1));
            uint32_t ah[4], al[4], bh[16], bl[16];
            ldsm4(ah, xhi_b + axo);
            ldsm4(al, xlo_b + axo);
            uint32_t wko = (uint32_t)(ks << 5);
            ldsm4(bh + 0,  whi_b + wko);
            ldsm4(bh + 4,  whi_b + wko + 16 * 528);
            ldsm4(bh + 8,  whi_b + wko + 32 * 528);
            ldsm4(bh + 12, whi_b + wko + 48 * 528);
            ldsm4(bl + 0,  wlo_b + wko);
            ldsm4(bl + 4,  wlo_b + wko + 16 * 528);
            ldsm4(bl + 8,  wlo_b + wko + 32 * 528);
            ldsm4(bl + 12, wlo_b + wko + 48 * 528);
#pragma unroll
            for (int g = 0; g < 4; ++g) {
                mma16816(c[2 * g],     ah, bh + 4 * g);
                mma16816(c[2 * g + 1], ah, bh + 4 * g + 2);
                mma16816(c[2 * g],     al, bh + 4 * g);
                mma16816(c[2 * g + 1], al, bh + 4 * g + 2);
                mma16816(c[2 * g],     ah, bl + 4 * g);
                mma16816(c[2 * g + 1], ah, bl + 4 * g + 2);
            }
        }

        int r0 = warp_p0 + (lane >> 2);
        int colb = (lane & 3) * 2;
        float va[16], vb[16];
#pragma unroll
        for (int n = 0; n < 8; ++n) {
            int cn = n * 8 + colb;
            va[2 * n]     = fast_tanh(c[n][0] + bsm[cn]);
            va[2 * n + 1] = fast_tanh(c[n][1] + bsm[cn + 1]);
            vb[2 * n]     = fast_tanh(c[n][2] + bsm[cn]);
            vb[2 * n + 1] = fast_tanh(c[n][3] + bsm[cn + 1]);
        }
        if (HAS_LN) {
            float s1a = 0.f, s2a = 0.f, s1b = 0.f, s2b = 0.f;
#pragma unroll
            for (int q = 0; q < 16; ++q) {
                s1a += va[q]; s2a += va[q] * va[q];
                s1b += vb[q]; s2b += vb[q] * vb[q];
            }
#pragma unroll
            for (int o = 1; o < 4; o <<= 1) {
                s1a += __shfl_xor_sync(0xffffffffu, s1a, o);
                s2a += __shfl_xor_sync(0xffffffffu, s2a, o);
                s1b += __shfl_xor_sync(0xffffffffu, s1b, o);
                s2b += __shfl_xor_sync(0xffffffffu, s2b, o);
            }
            float ma = s1a * (1.f / 64.f), mb = s1b * (1.f / 64.f);
            float ia = 1.f / sqrtf(s2a * (1.f / 64.f) - ma * ma + 1e-5f);
            float ib = 1.f / sqrtf(s2b * (1.f / 64.f) - mb * mb + 1e-5f);
            size_t rowa = (size_t)b * Lout + p0 + r0;
            __nv_bfloat16* oha = outhi + rowa * ND + colb;
            __nv_bfloat16* ola = outlo + rowa * ND + colb;
            __nv_bfloat16* ohb = oha + 8 * ND;
            __nv_bfloat16* olb = ola + 8 * ND;
#pragma unroll
            for (int n = 0; n < 8; ++n) {
                int cn = n * 8 + colb;
                float a0 = (va[2 * n]     - ma) * ia * gsm[cn]     + lbsm[cn];
                float a1 = (va[2 * n + 1] - ma) * ia * gsm[cn + 1] + lbsm[cn + 1];
                float b0 = (vb[2 * n]     - mb) * ib * gsm[cn]     + lbsm[cn];
                float b1 = (vb[2 * n + 1] - mb) * ib * gsm[cn + 1] + lbsm[cn + 1];
                __nv_bfloat16 h0 = __float2bfloat16(a0);
                __nv_bfloat16 h1 = __float2bfloat16(a1);
                __nv_bfloat16 h2 = __float2bfloat16(b0);
                __nv_bfloat16 h3 = __float2bfloat16(b1);
                *(__nv_bfloat162*)(oha + n * 8) = __nv_bfloat162(h0, h1);
                *(__nv_bfloat162*)(ohb + n * 8) = __nv_bfloat162(h2, h3);
                *(__nv_bfloat162*)(ola + n * 8) = __nv_bfloat162(
                    __float2bfloat16(a0 - __bfloat162float(h0)),
                    __float2bfloat16(a1 - __bfloat162float(h1)));
                *(__nv_bfloat162*)(olb + n * 8) = __nv_bfloat162(
                    __float2bfloat16(b0 - __bfloat162float(h2)),
                    __float2bfloat16(b1 - __bfloat162float(h3)));
            }
        } else {
            float* oa = outf + ((size_t)b * Lout + p0 + r0) * ND + colb;
            float* ob = oa + 8 * ND;
#pragma unroll
            for (int n = 0; n < 8; ++n) {
                *(float2*)(oa + n * 8) = make_float2(va[2 * n], va[2 * n + 1]);
                *(float2*)(ob + n * 8) = make_float2(vb[2 * n], vb[2 * n + 1]);
            }
        }
    }
}

extern "C" void kernel_launch(void* const* d_in, const int* in_sizes, int n_in,
                              void* d_out, int out_size) {
    const float* x   = (const float*)d_in[0];
    const float* tw3 = (const float*)d_in[1];
    const float* tb3 = (const float*)d_in[2];
    const float* tw5 = (const float*)d_in[3];
    const float* tb5 = (const float*)d_in[4];
    const float* tw7 = (const float*)d_in[5];
    const float* tb7 = (const float*)d_in[6];
    const float* tw9 = (const float*)d_in[7];
    const float* tb9 = (const float*)d_in[8];
    const float* cw1 = (const float*)d_in[9];
    const float* cb1 = (const float*)d_in[10];
    const float* cw2 = (const float*)d_in[11];
    const float* cb2 = (const float*)d_in[12];
    const float* cw3 = (const float*)d_in[13];
    const float* cb3 = (const float*)d_in[14];
    const float* lg1 = (const float*)d_in[15];
    const float* lb1 = (const float*)d_in[16];
    const float* lg2 = (const float*)d_in[17];
    const float* lb2 = (const float*)d_in[18];
    (void)in_sizes; (void)n_in; (void)out_size;

    void *wt_p, *h1_p, *h2_p;
    cudaGetSymbolAddress(&wt_p, g_wtb);
    cudaGetSymbolAddress(&h1_p, g_h1b);
    cudaGetSymbolAddress(&h2_p, g_h2b);
    __nv_bfloat16* wtb = (__nv_bfloat16*)wt_p;   // [3][2][64*264]
    __nv_bfloat16* h1hi = (__nv_bfloat16*)h1_p;
    __nv_bfloat16* h1lo = h1hi + (size_t)NB * NL1 * ND;
    __nv_bfloat16* h2hi = (__nv_bfloat16*)h2_p;
    __nv_bfloat16* h2lo = h2hi + (size_t)NB * NL2 * ND;

    cudaFuncSetAttribute((const void*)mma_stage<true>,
                         cudaFuncAttributeMaxDynamicSharedMemorySize, SMEM_BYTES);
    cudaFuncSetAttribute((const void*)mma_stage<false>,
                         cudaFuncAttributeMaxDynamicSharedMemorySize, SMEM_BYTES);
    const int TT_SMEM = (16384 + 34 * 64) * 4;        // 74,240 B
    cudaFuncSetAttribute((const void*)tt_kernel,
                         cudaFuncAttributeMaxDynamicSharedMemorySize, TT_SMEM);
    const int WEFF_SMEM = (16384 + 384 + 64) * 4;     // 67,328 B
    cudaFuncSetAttribute((const void*)weff_kernel,
                         cudaFuncAttributeMaxDynamicSharedMemorySize, WEFF_SMEM);

    const int PREP_N = NL0 * 32 + 32768 + 16384;
    prep_kernel<<<(PREP_N + 255) / 256, 256>>>(cw1, cw2, cw3);
    weff_kernel<<<1, 1024, WEFF_SMEM>>>(cw1, tw3, tb3, tw5, tb5, tw7, tb7, tw9, tb9);
    tt_kernel<<<128, 256, TT_SMEM>>>(cb1);

    // stage1: composed 12-tap conv + TT table -> tanh -> LN -> bf16 planes
    dim3 fg(NL1 / 128, NB);
    front_kernel<<<fg, 256>>>(x, h1hi, h1lo, lg1, lb1);

    const int PL = 64 * 264;   // bf16 elements per W plane
    mma_stage<true><<<148, 512, SMEM_BYTES>>>(
        h1hi, h1lo, nullptr, h2hi, h2lo,
        wtb + 1 * 2 * PL, wtb + (1 * 2 + 1) * PL, cb2, lg2, lb2,
        NL1, NL2, NB * (NL2 / 256));
    mma_stage<false><<<148, 512, SMEM_BYTES>>>(
        h2hi, h2lo, (float*)d_out, nullptr, nullptr,
        wtb + 2 * 2 * PL, wtb + (2 * 2 + 1) * PL, cb3, nullptr, nullptr,
        NL2, NL3, NB * (NL3 / 256));
}

// round 16
// speedup vs baseline: 1.5672x; 1.0587x over previous
#include <cuda_runtime.h>
#include <cuda_bf16.h>
#include <math.h>
#include <stdint.h>

#define NB 128
#define ND 64
#define NL0 4096
#define NL1 2048
#define NL2 1024
#define NL3 512

// Scratch (static device allocations allowed; cudaMalloc is not)
__device__ float g_pe[NL0 * ND];                          // 1 MB positional table
__device__ float g_w1t[256 * 64];                         // W1 transposed [k=kk*64+ci][co]
__device__ float g_weff[3][64][12];                       // composed 12-tap conv weights (3 edge cases)
__device__ float g_tbp[4][64];                            // per-kk token-bias projection through W1
__device__ float g_tt[NL1 * 64];                          // TT[p][co] = W1*pe + W1*tb + b1 (case-aware)
__device__ __nv_bfloat16 g_wtb[3][2][64 * 264];           // W hi/lo planes, row stride 264 bf16 (528B)
__device__ __nv_bfloat16 g_h1b[2][(size_t)NB * NL1 * ND]; // h1 as bf16 hi/lo planes
__device__ __nv_bfloat16 g_h2b[2][(size_t)NB * NL2 * ND]; // h2 as bf16 hi/lo planes

__device__ __forceinline__ uint32_t smem_u32(const void* p) {
    uint32_t a;
    asm("{ .reg .u64 t; cvta.to.shared.u64 t, %1; cvt.u32.u64 %0, t; }" : "=r"(a) : "l"(p));
    return a;
}
__device__ __forceinline__ void ldsm4(uint32_t* r, uint32_t a) {
    asm volatile("ldmatrix.sync.aligned.m8n8.x4.shared.b16 {%0,%1,%2,%3}, [%4];"
                 : "=r"(r[0]), "=r"(r[1]), "=r"(r[2]), "=r"(r[3]) : "r"(a));
}
__device__ __forceinline__ void mma16816(float* c, const uint32_t* a, const uint32_t* b) {
    asm volatile("mma.sync.aligned.m16n8k16.row.col.f32.bf16.bf16.f32 "
                 "{%0,%1,%2,%3}, {%4,%5,%6,%7}, {%8,%9}, {%0,%1,%2,%3};"
                 : "+f"(c[0]), "+f"(c[1]), "+f"(c[2]), "+f"(c[3])
                 : "r"(a[0]), "r"(a[1]), "r"(a[2]), "r"(a[3]), "r"(b[0]), "r"(b[1]));
}
// MUFU-based tanh: abs err ~1ulp-of-1 (~6e-8); far under the 1e-3 budget.
__device__ __forceinline__ float fast_tanh(float x) {
    float e = __expf(-2.f * fabsf(x));
    float t = __fdividef(1.f - e, 1.f + e);
    return copysignf(t, x);
}
__device__ __forceinline__ uint32_t pack_bf2(float a, float b) {
    __nv_bfloat162 v(__float2bfloat16(a), __float2bfloat16(b));
    return *(uint32_t*)&v;
}

// ---------------------------------------------------------------------------
// Fused prep: PE table (fp32 trig), stage2/3 weight split to bf16 hi/lo
// planes, W1 transpose. Index-partitioned.
// ---------------------------------------------------------------------------
__global__ void prep_kernel(const float* __restrict__ w1,
                            const float* __restrict__ w2,
                            const float* __restrict__ w3) {
    int idx = blockIdx.x * blockDim.x + threadIdx.x;
    if (idx < NL0 * 32) {
        int l = idx >> 5, i = idx & 31;
        float argf = (float)(2 * i) * (float)(-log(10000.0) / 64.0);
        float divf = __expf(argf);
        float ang  = (float)l * divf;
        g_pe[l * ND + 2 * i]     = sinf(ang);
        g_pe[l * ND + 2 * i + 1] = cosf(ang);
    } else if (idx < NL0 * 32 + 32768) {
        int r = idx - NL0 * 32;
        int s = r >> 14;                      // 0 -> stage2, 1 -> stage3
        int rem = r & 16383;                  // co*256 + ci*4 + kk
        int co = rem >> 8;
        int ci = (rem >> 2) & 63;
        int kk = rem & 3;
        const float* w = (s == 0) ? w2 : w3;
        float v = w[rem];
        __nv_bfloat16 hi = __float2bfloat16(v);
        __nv_bfloat16 lo = __float2bfloat16(v - __bfloat162float(hi));
        int off = co * 264 + kk * 64 + ci;
        g_wtb[s + 1][0][off] = hi;
        g_wtb[s + 1][1][off] = lo;
    } else if (idx < NL0 * 32 + 32768 + 16384) {
        int r = idx - NL0 * 32 - 32768;
        int co = r >> 8;
        int ci = (r >> 2) & 63;
        int kk = r & 3;
        g_w1t[(kk * 64 + ci) * 64 + co] = w1[r];
    }
}

// ---------------------------------------------------------------------------
// Composed front weights (single block, smem-staged w1 + token weights).
// ---------------------------------------------------------------------------
__global__ void weff_kernel(const float* __restrict__ w1,
                            const float* __restrict__ tw3, const float* __restrict__ tb3,
                            const float* __restrict__ tw5, const float* __restrict__ tb5,
                            const float* __restrict__ tw7, const float* __restrict__ tb7,
                            const float* __restrict__ tw9, const float* __restrict__ tb9) {
    extern __shared__ float sm[];
    float* w1s = sm;            // 16384
    float* tws = sm + 16384;    // 384
    float* tbs = sm + 16768;    // 64
    int tid = threadIdx.x;      // 1024 threads
    for (int i = tid; i < 16384; i += 1024) w1s[i] = w1[i];
    if (tid < 48)  tws[tid]       = tw3[tid];
    if (tid < 80)  tws[48 + tid]  = tw5[tid];
    if (tid < 112) tws[128 + tid] = tw7[tid];
    if (tid < 144) tws[240 + tid] = tw9[tid];
    if (tid < 16) {
        tbs[tid]      = tb3[tid];
        tbs[16 + tid] = tb5[tid];
        tbs[32 + tid] = tb7[tid];
        tbs[48 + tid] = tb9[tid];
    }
    __syncthreads();
    for (int idx = tid; idx < 2560; idx += 1024) {
        if (idx < 2304) {
            int cse = idx / 768;
            int rem = idx - cse * 768;
            int co = rem / 12, tau = rem - co * 12;
            float acc = 0.f;
            for (int kk = 0; kk < 4; ++kk) {
                if (cse == 1 && kk == 0) continue;
                if (cse == 2 && kk == 3) continue;
                for (int ci = 0; ci < 64; ++ci) {
                    int g = ci & 3, j = ci >> 2;
                    int pad = g + 1, ks = 3 + 2 * g;
                    int t = tau - 4 - kk + pad;
                    if (t < 0 || t >= ks) continue;
                    int two = (g == 0) ? 0 : (g == 1) ? 48 : (g == 2) ? 128 : 240;
                    acc += w1s[co * 256 + ci * 4 + kk] * tws[two + j * ks + t];
                }
            }
            g_weff[cse][co][tau] = acc;
        } else {
            int r = idx - 2304;
            int kk = r >> 6, co = r & 63;
            float acc = 0.f;
            for (int ci = 0; ci < 64; ++ci)
                acc += w1s[co * 256 + ci * 4 + kk] * tbs[(ci & 3) * 16 + (ci >> 2)];
            g_tbp[kk][co] = acc;
        }
    }
}

// ---------------------------------------------------------------------------
// TT[p][co] = b1[co] + sum_{kk valid} ( tbp[kk][co] + sum_ci W1[co,ci,kk]*pe[2p-1+kk][ci] )
// ---------------------------------------------------------------------------
__global__ void tt_kernel(const float* __restrict__ cb1) {
    extern __shared__ float sm[];
    float* w1ts = sm;              // 16384
    float* pes  = sm + 16384;      // 34*64
    int tid = threadIdx.x;
    int p0 = blockIdx.x * 16;
    for (int i = tid; i < 16384; i += 256) w1ts[i] = g_w1t[i];
    for (int i = tid; i < 34 * 64; i += 256) {
        int r = i >> 6, ci = i & 63;
        int g = 2 * p0 - 1 + r;
        pes[i] = (g >= 0 && g < NL0) ? g_pe[g * 64 + ci] : 0.f;
    }
    __syncthreads();
    int co = tid & 63, py = tid >> 6;
    float acc[4] = {0.f, 0.f, 0.f, 0.f};
    for (int kk = 0; kk < 4; ++kk) {
#pragma unroll 8
        for (int ci = 0; ci < 64; ++ci) {
            float w = w1ts[(kk * 64 + ci) * 64 + co];
#pragma unroll
            for (int i = 0; i < 4; ++i)
                acc[i] += w * pes[(2 * (py * 4 + i) + kk) * 64 + ci];
        }
    }
    float tsum = g_tbp[0][co] + g_tbp[1][co] + g_tbp[2][co] + g_tbp[3][co];
    float bb = cb1[co];
#pragma unroll
    for (int i = 0; i < 4; ++i) {
        int p = p0 + py * 4 + i;
        float bias = bb + tsum;
        if (p == 0)       bias -= g_tbp[0][co];
        if (p == NL1 - 1) bias -= g_tbp[3][co];
        g_tt[p * 64 + co] = acc[i] + bias;
    }
}

// ---------------------------------------------------------------------------
// Stage1 "front": out1 = LN(tanh(conv12(Weff,x) + TT)) as bf16 hi/lo planes.
// 256 threads, tile 128 positions, thread = 4 co x 8 pos. Epilogue is phase-
// structured: batched tt loads (8-way MLP) -> all tanh -> interleaved shfl
// reductions (8 independent chains) -> stores. Grid (16, NB).
// ---------------------------------------------------------------------------
__global__ void __launch_bounds__(256)
front_kernel(const float* __restrict__ x,
             __nv_bfloat16* __restrict__ outhi, __nv_bfloat16* __restrict__ outlo,
             const float* __restrict__ lng, const float* __restrict__ lnb) {
    __shared__ float xs[266];
    __shared__ float wsm[768];
    __shared__ float gsm[64], lbsm[64];
    int tid = threadIdx.x;
    int t = blockIdx.x, b = blockIdx.y;
    int p0 = t * 128;
    if (tid < 64) { gsm[tid] = lng[tid]; lbsm[tid] = lnb[tid]; }
    for (int i = tid; i < 768; i += 256) wsm[i] = ((const float*)g_weff)[i]; // case 0
    const float* xb = x + (size_t)b * NL0;
    int base = 2 * p0 - 5;
    for (int i = tid; i < 266; i += 256) {
        int gi = base + i;
        xs[i] = (gi >= 0 && gi < NL0) ? xb[gi] : 0.f;
    }
    __syncthreads();

    int tx = tid & 15, ty = tid >> 4;
    int co0 = tx * 4;
    float wr[4][12];
#pragma unroll
    for (int c = 0; c < 4; ++c)
#pragma unroll
        for (int tau = 0; tau < 12; ++tau) wr[c][tau] = wsm[(co0 + c) * 12 + tau];
    float xr[26];
#pragma unroll
    for (int i = 0; i < 26; ++i) xr[i] = xs[16 * ty + i];

    float acc[8][4];
#pragma unroll
    for (int j = 0; j < 8; ++j) {
#pragma unroll
        for (int c = 0; c < 4; ++c) acc[j][c] = 0.f;
#pragma unroll
        for (int tau = 0; tau < 12; ++tau) {
            float xv = xr[2 * j + tau];
#pragma unroll
            for (int c = 0; c < 4; ++c) acc[j][c] = fmaf(wr[c][tau], xv, acc[j][c]);
        }
    }
    // edge positions use case-1 / case-2 composed weights
    if (t == 0 && ty == 0) {
#pragma unroll
        for (int c = 0; c < 4; ++c) {
            float a = 0.f;
            for (int tau = 0; tau < 12; ++tau) a = fmaf(g_weff[1][co0 + c][tau], xr[tau], a);
            acc[0][c] = a;
        }
    }
    if (t == 15 && ty == 15) {
#pragma unroll
        for (int c = 0; c < 4; ++c) {
            float a = 0.f;
            for (int tau = 0; tau < 12; ++tau) a = fmaf(g_weff[2][co0 + c][tau], xr[14 + tau], a);
            acc[7][c] = a;
        }
    }

    // ---- epilogue, phase-structured for ILP ----
    int pb = p0 + ty * 8;
    float4 tt[8];
#pragma unroll
    for (int j = 0; j < 8; ++j)
        tt[j] = *(const float4*)(g_tt + (pb + j) * 64 + co0);   // 8-way MLP batch

    float v[8][4];
#pragma unroll
    for (int j = 0; j < 8; ++j) {
        v[j][0] = fast_tanh(acc[j][0] + tt[j].x);
        v[j][1] = fast_tanh(acc[j][1] + tt[j].y);
        v[j][2] = fast_tanh(acc[j][2] + tt[j].z);
        v[j][3] = fast_tanh(acc[j][3] + tt[j].w);
    }
    float s1[8], s2[8];
#pragma unroll
    for (int j = 0; j < 8; ++j) {
        s1[j] = v[j][0] + v[j][1] + v[j][2] + v[j][3];
        s2[j] = v[j][0] * v[j][0] + v[j][1] * v[j][1]
              + v[j][2] * v[j][2] + v[j][3] * v[j][3];
    }
#pragma unroll
    for (int o = 1; o < 16; o <<= 1) {
#pragma unroll
        for (int j = 0; j < 8; ++j) {          // 8 independent chains per level
            s1[j] += __shfl_xor_sync(0xffffffffu, s1[j], o);
            s2[j] += __shfl_xor_sync(0xffffffffu, s2[j], o);
        }
    }
#pragma unroll
    for (int j = 0; j < 8; ++j) {
        float m   = s1[j] * (1.f / 64.f);
        float var = s2[j] * (1.f / 64.f) - m * m;
        float inv = 1.f / sqrtf(var + 1e-5f);
        float o0 = (v[j][0] - m) * inv * gsm[co0 + 0] + lbsm[co0 + 0];
        float o1 = (v[j][1] - m) * inv * gsm[co0 + 1] + lbsm[co0 + 1];
        float o2 = (v[j][2] - m) * inv * gsm[co0 + 2] + lbsm[co0 + 2];
        float o3 = (v[j][3] - m) * inv * gsm[co0 + 3] + lbsm[co0 + 3];
        size_t ro = ((size_t)b * NL1 + pb + j) * ND + co0;
        __nv_bfloat16 h0 = __float2bfloat16(o0);
        __nv_bfloat16 h1 = __float2bfloat16(o1);
        __nv_bfloat16 h2 = __float2bfloat16(o2);
        __nv_bfloat16 h3 = __float2bfloat16(o3);
        uint32_t hi01, hi23;
        { __nv_bfloat162 q(h0, h1); hi01 = *(uint32_t*)&q; }
        { __nv_bfloat162 q(h2, h3); hi23 = *(uint32_t*)&q; }
        *(uint2*)(outhi + ro) = make_uint2(hi01, hi23);
        uint32_t lo01 = pack_bf2(o0 - __bfloat162float(h0), o1 - __bfloat162float(h1));
        uint32_t lo23 = pack_bf2(o2 - __bfloat162float(h2), o3 - __bfloat162float(h3));
        *(uint2*)(outlo + ro) = make_uint2(lo01, lo23);
    }
}

// ---------------------------------------------------------------------------
// Stages 2/3 as mma.sync bf16 GEMM. NEW: warp-private X slots (34 rows/warp,
// halo duplicated) -> ZERO per-tile block barriers; a warp's fill overlaps
// other warps' mma. Bank-conflict freedom of the (slot&8) xor swizzle is
// base-offset invariant, so the per-warp slot offset preserves it.
// ---------------------------------------------------------------------------
#define X_SLOTS  544
#define X_STRIDE 144
#define SM_XHI   0
#define SM_XLO   (X_SLOTS * X_STRIDE)                 // 78,336
#define SM_WHI   (2 * X_SLOTS * X_STRIDE)             // 156,672
#define SM_WLO   (SM_WHI + 64 * 528)                  // 190,464
#define SM_F     (SM_WLO + 64 * 528)                  // 224,256
#define SMEM_BYTES (SM_F + 256 * 4)                   // 225,280

template <bool HAS_LN>
__global__ void __launch_bounds__(512, 1)
mma_stage(const __nv_bfloat16* __restrict__ inhi, const __nv_bfloat16* __restrict__ inlo,
          float* __restrict__ outf,
          __nv_bfloat16* __restrict__ outhi, __nv_bfloat16* __restrict__ outlo,
          const __nv_bfloat16* __restrict__ whi_g, const __nv_bfloat16* __restrict__ wlo_g,
          const float* __restrict__ bias, const float* __restrict__ lng,
          const float* __restrict__ lnb,
          int Lin, int Lout, int numTiles) {
    extern __shared__ char smem[];
    int tid = threadIdx.x, lane = tid & 31, wid = tid >> 5;

    {
        const uint4* s0 = (const uint4*)whi_g;
        const uint4* s1 = (const uint4*)wlo_g;
        uint4* d0 = (uint4*)(smem + SM_WHI);
        uint4* d1 = (uint4*)(smem + SM_WLO);
        for (int i = tid; i < 2112; i += 512) { d0[i] = s0[i]; d1[i] = s1[i]; }
    }
    float* fm   = (float*)(smem + SM_F);
    float* bsm  = fm;
    float* gsm  = fm + 64;
    float* lbsm = fm + 128;
    if (tid < 64) {
        bsm[tid] = bias[tid];
        if (HAS_LN) { gsm[tid] = lng[tid]; lbsm[tid] = lnb[tid]; }
    }
    __syncthreads();   // W planes + params ready (read-only afterwards)

    int warp_p0 = wid * 16;
    int arow   = lane & 15;
    int slot2  = 34 * wid + 2 * arow;                  // + kk at use
    int acib   = (lane >> 4) << 4;
    int wrow   = (lane & 7) + ((lane >> 4) << 3);
    uint32_t wbyte = (uint32_t)(wrow * 528 + (((lane >> 3) & 1) << 4));
    uint32_t xhi_b = smem_u32(smem + SM_XHI);
    uint32_t xlo_b = smem_u32(smem + SM_XLO);
    uint32_t whi_b = smem_u32(smem + SM_WHI) + wbyte;
    uint32_t wlo_b = smem_u32(smem + SM_WLO) + wbyte;

    int tilesPerB = Lout >> 8;
    for (int tile = blockIdx.x; tile < numTiles; tile += gridDim.x) {
        int b = tile / tilesPerB;
        int t = tile - b * tilesPerB;
        int p0 = t << 8;
        int g0 = 2 * p0 - 1;

        // ---- warp-private fill of this warp's 34 X rows (hi+lo planes) ----
        __syncwarp();   // prior tile's ldmatrix reads complete across lanes
        {
            const __nv_bfloat16* ihb = inhi + (size_t)b * Lin * ND;
            const __nv_bfloat16* ilb = inlo + (size_t)b * Lin * ND;
            const uint4 z4 = make_uint4(0u, 0u, 0u, 0u);
            int rbase = g0 + 32 * wid;
            for (int i = lane; i < 272; i += 32) {
                int j  = i >> 3;
                int cb = (i & 7) << 3;
                int gg = rbase + j;
                uint4 vh = z4, vl = z4;
                if (gg >= 0 && gg < Lin) {
                    size_t go = (size_t)gg * ND + cb;
                    vh = *(const uint4*)(ihb + go);
                    vl = *(const uint4*)(ilb + go);
                }
                int slot = 34 * wid + j;
                uint32_t xo = (uint32_t)(slot * X_STRIDE) +
                              (uint32_t)((cb * 2) ^ ((slot & 8) << 1));
                *(uint4*)(smem + SM_XHI + xo) = vh;
                *(uint4*)(smem + SM_XLO + xo) = vl;
            }
        }
        __syncwarp();   // fill visible to all lanes before ldmatrix

        float c[8][4];
#pragma unroll
        for (int n = 0; n < 8; ++n)
#pragma unroll
            for (int q = 0; q < 4; ++q) c[n][q] = 0.f;

#pragma unroll 2
        for (int ks = 0; ks < 16; ++ks) {
            int kk = ks >> 2;
            int slot = slot2 + kk;
            uint32_t axo = (uint32_t)(slot * X_STRIDE) +
                           (uint32_t)((((ks & 3) << 5) + acib) ^ ((slot & 8) << 1));
            uint32_t ah[4], al[4], bh[16], bl[16];
            ldsm4(ah, xhi_b + axo);
            ldsm4(al, xlo_b + axo);
            uint32_t wko = (uint32_t)(ks << 5);
            ldsm4(bh + 0,  whi_b + wko);
            ldsm4(bh + 4,  whi_b + wko + 16 * 528);
            ldsm4(bh + 8,  whi_b + wko + 32 * 528);
            ldsm4(bh + 12, whi_b + wko + 48 * 528);
            ldsm4(bl + 0,  wlo_b + wko);
            ldsm4(bl + 4,  wlo_b + wko + 16 * 528);
            ldsm4(bl + 8,  wlo_b + wko + 32 * 528);
            ldsm4(bl + 12, wlo_b + wko + 48 * 528);
#pragma unroll
            for (int g = 0; g < 4; ++g) {
                mma16816(c[2 * g],     ah, bh + 4 * g);
                mma16816(c[2 * g + 1], ah, bh + 4 * g + 2);
                mma16816(c[2 * g],     al, bh + 4 * g);
                mma16816(c[2 * g + 1], al, bh + 4 * g + 2);
                mma16816(c[2 * g],     ah, bl + 4 * g);
                mma16816(c[2 * g + 1], ah, bl + 4 * g + 2);
            }
        }

        int r0 = warp_p0 + (lane >> 2);
        int colb = (lane & 3) * 2;
        float va[16], vb[16];
#pragma unroll
        for (int n = 0; n < 8; ++n) {
            int cn = n * 8 + colb;
            va[2 * n]     = fast_tanh(c[n][0] + bsm[cn]);
            va[2 * n + 1] = fast_tanh(c[n][1] + bsm[cn + 1]);
            vb[2 * n]     = fast_tanh(c[n][2] + bsm[cn]);
            vb[2 * n + 1] = fast_tanh(c[n][3] + bsm[cn + 1]);
        }
        if (HAS_LN) {
            float s1a = 0.f, s2a = 0.f, s1b = 0.f, s2b = 0.f;
#pragma unroll
            for (int q = 0; q < 16; ++q) {
                s1a += va[q]; s2a += va[q] * va[q];
                s1b += vb[q]; s2b += vb[q] * vb[q];
            }
#pragma unroll
            for (int o = 1; o < 4; o <<= 1) {
                s1a += __shfl_xor_sync(0xffffffffu, s1a, o);
                s2a += __shfl_xor_sync(0xffffffffu, s2a, o);
                s1b += __shfl_xor_sync(0xffffffffu, s1b, o);
                s2b += __shfl_xor_sync(0xffffffffu, s2b, o);
            }
            float ma = s1a * (1.f / 64.f), mb = s1b * (1.f / 64.f);
            float ia = 1.f / sqrtf(s2a * (1.f / 64.f) - ma * ma + 1e-5f);
            float ib = 1.f / sqrtf(s2b * (1.f / 64.f) - mb * mb + 1e-5f);
            size_t rowa = (size_t)b * Lout + p0 + r0;
            __nv_bfloat16* oha = outhi + rowa * ND + colb;
            __nv_bfloat16* ola = outlo + rowa * ND + colb;
            __nv_bfloat16* ohb = oha + 8 * ND;
            __nv_bfloat16* olb = ola + 8 * ND;
#pragma unroll
            for (int n = 0; n < 8; ++n) {
                int cn = n * 8 + colb;
                float a0 = (va[2 * n]     - ma) * ia * gsm[cn]     + lbsm[cn];
                float a1 = (va[2 * n + 1] - ma) * ia * gsm[cn + 1] + lbsm[cn + 1];
                float b0 = (vb[2 * n]     - mb) * ib * gsm[cn]     + lbsm[cn];
                float b1 = (vb[2 * n + 1] - mb) * ib * gsm[cn + 1] + lbsm[cn + 1];
                __nv_bfloat16 h0 = __float2bfloat16(a0);
                __nv_bfloat16 h1 = __float2bfloat16(a1);
                __nv_bfloat16 h2 = __float2bfloat16(b0);
                __nv_bfloat16 h3 = __float2bfloat16(b1);
                *(__nv_bfloat162*)(oha + n * 8) = __nv_bfloat162(h0, h1);
                *(__nv_bfloat162*)(ohb + n * 8) = __nv_bfloat162(h2, h3);
                *(__nv_bfloat162*)(ola + n * 8) = __nv_bfloat162(
                    __float2bfloat16(a0 - __bfloat162float(h0)),
                    __float2bfloat16(a1 - __bfloat162float(h1)));
                *(__nv_bfloat162*)(olb + n * 8) = __nv_bfloat162(
                    __float2bfloat16(b0 - __bfloat162float(h2)),
                    __float2bfloat16(b1 - __bfloat162float(h3)));
            }
        } else {
            float* oa = outf + ((size_t)b * Lout + p0 + r0) * ND + colb;
            float* ob = oa + 8 * ND;
#pragma unroll
            for (int n = 0; n < 8; ++n) {
                *(float2*)(oa + n * 8) = make_float2(va[2 * n], va[2 * n + 1]);
                *(float2*)(ob + n * 8) = make_float2(vb[2 * n], vb[2 * n + 1]);
            }
        }
    }
}

extern "C" void kernel_launch(void* const* d_in, const int* in_sizes, int n_in,
                              void* d_out, int out_size) {
    const float* x   = (const float*)d_in[0];
    const float* tw3 = (const float*)d_in[1];
    const float* tb3 = (const float*)d_in[2];
    const float* tw5 = (const float*)d_in[3];
    const float* tb5 = (const float*)d_in[4];
    const float* tw7 = (const float*)d_in[5];
    const float* tb7 = (const float*)d_in[6];
    const float* tw9 = (const float*)d_in[7];
    const float* tb9 = (const float*)d_in[8];
    const float* cw1 = (const float*)d_in[9];
    const float* cb1 = (const float*)d_in[10];
    const float* cw2 = (const float*)d_in[11];
    const float* cb2 = (const float*)d_in[12];
    const float* cw3 = (const float*)d_in[13];
    const float* cb3 = (const float*)d_in[14];
    const float* lg1 = (const float*)d_in[15];
    const float* lb1 = (const float*)d_in[16];
    const float* lg2 = (const float*)d_in[17];
    const float* lb2 = (const float*)d_in[18];
    (void)in_sizes; (void)n_in; (void)out_size;

    void *wt_p, *h1_p, *h2_p;
    cudaGetSymbolAddress(&wt_p, g_wtb);
    cudaGetSymbolAddress(&h1_p, g_h1b);
    cudaGetSymbolAddress(&h2_p, g_h2b);
    __nv_bfloat16* wtb = (__nv_bfloat16*)wt_p;   // [3][2][64*264]
    __nv_bfloat16* h1hi = (__nv_bfloat16*)h1_p;
    __nv_bfloat16* h1lo = h1hi + (size_t)NB * NL1 * ND;
    __nv_bfloat16* h2hi = (__nv_bfloat16*)h2_p;
    __nv_bfloat16* h2lo = h2hi + (size_t)NB * NL2 * ND;

    cudaFuncSetAttribute((const void*)mma_stage<true>,
                         cudaFuncAttributeMaxDynamicSharedMemorySize, SMEM_BYTES);
    cudaFuncSetAttribute((const void*)mma_stage<false>,
                         cudaFuncAttributeMaxDynamicSharedMemorySize, SMEM_BYTES);
    const int TT_SMEM = (16384 + 34 * 64) * 4;        // 74,240 B
    cudaFuncSetAttribute((const void*)tt_kernel,
                         cudaFuncAttributeMaxDynamicSharedMemorySize, TT_SMEM);
    const int WEFF_SMEM = (16384 + 384 + 64) * 4;     // 67,328 B
    cudaFuncSetAttribute((const void*)weff_kernel,
                         cudaFuncAttributeMaxDynamicSharedMemorySize, WEFF_SMEM);

    const int PREP_N = NL0 * 32 + 32768 + 16384;
    prep_kernel<<<(PREP_N + 255) / 256, 256>>>(cw1, cw2, cw3);
    weff_kernel<<<1, 1024, WEFF_SMEM>>>(cw1, tw3, tb3, tw5, tb5, tw7, tb7, tw9, tb9);
    tt_kernel<<<128, 256, TT_SMEM>>>(cb1);

    // stage1: composed 12-tap conv + TT table -> tanh -> LN -> bf16 planes
    dim3 fg(NL1 / 128, NB);
    front_kernel<<<fg, 256>>>(x, h1hi, h1lo, lg1, lb1);

    const int PL = 64 * 264;   // bf16 elements per W plane
    mma_stage<true><<<148, 512, SMEM_BYTES>>>(
        h1hi, h1lo, nullptr, h2hi, h2lo,
        wtb + 1 * 2 * PL, wtb + (1 * 2 + 1) * PL, cb2, lg2, lb2,
        NL1, NL2, NB * (NL2 / 256));
    mma_stage<false><<<148, 512, SMEM_BYTES>>>(
        h2hi, h2lo, (float*)d_out, nullptr, nullptr,
        wtb + 2 * 2 * PL, wtb + (2 * 2 + 1) * PL, cb3, nullptr, nullptr,
        NL2, NL3, NB * (NL3 / 256));
}

// round 17
// speedup vs baseline: 1.5868x; 1.0125x over previous
#include <cuda_runtime.h>
#include <cuda_bf16.h>
#include <math.h>
#include <stdint.h>

#define NB 128
#define ND 64
#define NL0 4096
#define NL1 2048
#define NL2 1024
#define NL3 512

// Scratch (static device allocations allowed; cudaMalloc is not)
__device__ float g_pe[NL0 * ND];                          // 1 MB positional table
__device__ float g_w1t[256 * 64];                         // W1 transposed [k=kk*64+ci][co]
__device__ float g_weff[3][64][12];                       // composed 12-tap conv weights (3 edge cases)
__device__ float g_tbp[4][64];                            // per-kk token-bias projection through W1
__device__ float g_tt[NL1 * 64];                          // TT[p][co] = W1*pe + W1*tb + b1 (case-aware)
__device__ __nv_bfloat16 g_wtb[3][2][64 * 264];           // W hi/lo planes, row stride 264 bf16 (528B)
__device__ __nv_bfloat16 g_h1b[2][(size_t)NB * NL1 * ND]; // h1 as bf16 hi/lo planes
__device__ __nv_bfloat16 g_h2b[2][(size_t)NB * NL2 * ND]; // h2 as bf16 hi/lo planes

__device__ __forceinline__ uint32_t smem_u32(const void* p) {
    uint32_t a;
    asm("{ .reg .u64 t; cvta.to.shared.u64 t, %1; cvt.u32.u64 %0, t; }" : "=r"(a) : "l"(p));
    return a;
}
__device__ __forceinline__ void ldsm4(uint32_t* r, uint32_t a) {
    asm volatile("ldmatrix.sync.aligned.m8n8.x4.shared.b16 {%0,%1,%2,%3}, [%4];"
                 : "=r"(r[0]), "=r"(r[1]), "=r"(r[2]), "=r"(r[3]) : "r"(a));
}
__device__ __forceinline__ void mma16816(float* c, const uint32_t* a, const uint32_t* b) {
    asm volatile("mma.sync.aligned.m16n8k16.row.col.f32.bf16.bf16.f32 "
                 "{%0,%1,%2,%3}, {%4,%5,%6,%7}, {%8,%9}, {%0,%1,%2,%3};"
                 : "+f"(c[0]), "+f"(c[1]), "+f"(c[2]), "+f"(c[3])
                 : "r"(a[0]), "r"(a[1]), "r"(a[2]), "r"(a[3]), "r"(b[0]), "r"(b[1]));
}
// HW tanh (MUFU.TANH): rel err ~2^-11. Used in FRONT only — its error is
// RMS-averaged by the two downstream GEMM stages (final output ~1e-4 rms).
__device__ __forceinline__ float tanh_hw(float x) {
    float y;
    asm("tanh.approx.f32 %0, %1;" : "=f"(y) : "f"(x));
    return y;
}
// Exact-path tanh (6 instr): 1 - 2/(1+e^{2x}). Used in mma epilogues.
__device__ __forceinline__ float fast_tanh(float x) {
    float e = __expf(x + x);
    return 1.f - __fdividef(2.f, 1.f + e);
}
// Pack two floats to bf16x2 in ONE cvt (RN, same rounding as __float2bfloat16).
__device__ __forceinline__ uint32_t cvt_bf2(float lo, float hi) {
    uint32_t r;
    asm("cvt.rn.bf16x2.f32 %0, %1, %2;" : "=r"(r) : "f"(hi), "f"(lo));
    return r;
}
__device__ __forceinline__ float bf_lo_f(uint32_t v) { return __uint_as_float(v << 16); }
__device__ __forceinline__ float bf_hi_f(uint32_t v) { return __uint_as_float(v & 0xffff0000u); }

// ---------------------------------------------------------------------------
// Fused prep: PE table (fp32 trig), stage2/3 weight split to bf16 hi/lo
// planes, W1 transpose. Index-partitioned.
// ---------------------------------------------------------------------------
__global__ void prep_kernel(const float* __restrict__ w1,
                            const float* __restrict__ w2,
                            const float* __restrict__ w3) {
    int idx = blockIdx.x * blockDim.x + threadIdx.x;
    if (idx < NL0 * 32) {
        int l = idx >> 5, i = idx & 31;
        float argf = (float)(2 * i) * (float)(-log(10000.0) / 64.0);
        float divf = __expf(argf);
        float ang  = (float)l * divf;
        g_pe[l * ND + 2 * i]     = sinf(ang);
        g_pe[l * ND + 2 * i + 1] = cosf(ang);
    } else if (idx < NL0 * 32 + 32768) {
        int r = idx - NL0 * 32;
        int s = r >> 14;                      // 0 -> stage2, 1 -> stage3
        int rem = r & 16383;                  // co*256 + ci*4 + kk
        int co = rem >> 8;
        int ci = (rem >> 2) & 63;
        int kk = rem & 3;
        const float* w = (s == 0) ? w2 : w3;
        float v = w[rem];
        __nv_bfloat16 hi = __float2bfloat16(v);
        __nv_bfloat16 lo = __float2bfloat16(v - __bfloat162float(hi));
        int off = co * 264 + kk * 64 + ci;
        g_wtb[s + 1][0][off] = hi;
        g_wtb[s + 1][1][off] = lo;
    } else if (idx < NL0 * 32 + 32768 + 16384) {
        int r = idx - NL0 * 32 - 32768;
        int co = r >> 8;
        int ci = (r >> 2) & 63;
        int kk = r & 3;
        g_w1t[(kk * 64 + ci) * 64 + co] = w1[r];
    }
}

// ---------------------------------------------------------------------------
// Composed front weights (single block, smem-staged w1 + token weights).
// ---------------------------------------------------------------------------
__global__ void weff_kernel(const float* __restrict__ w1,
                            const float* __restrict__ tw3, const float* __restrict__ tb3,
                            const float* __restrict__ tw5, const float* __restrict__ tb5,
                            const float* __restrict__ tw7, const float* __restrict__ tb7,
                            const float* __restrict__ tw9, const float* __restrict__ tb9) {
    extern __shared__ float sm[];
    float* w1s = sm;            // 16384
    float* tws = sm + 16384;    // 384
    float* tbs = sm + 16768;    // 64
    int tid = threadIdx.x;      // 1024 threads
    for (int i = tid; i < 16384; i += 1024) w1s[i] = w1[i];
    if (tid < 48)  tws[tid]       = tw3[tid];
    if (tid < 80)  tws[48 + tid]  = tw5[tid];
    if (tid < 112) tws[128 + tid] = tw7[tid];
    if (tid < 144) tws[240 + tid] = tw9[tid];
    if (tid < 16) {
        tbs[tid]      = tb3[tid];
        tbs[16 + tid] = tb5[tid];
        tbs[32 + tid] = tb7[tid];
        tbs[48 + tid] = tb9[tid];
    }
    __syncthreads();
    for (int idx = tid; idx < 2560; idx += 1024) {
        if (idx < 2304) {
            int cse = idx / 768;
            int rem = idx - cse * 768;
            int co = rem / 12, tau = rem - co * 12;
            float acc = 0.f;
            for (int kk = 0; kk < 4; ++kk) {
                if (cse == 1 && kk == 0) continue;
                if (cse == 2 && kk == 3) continue;
                for (int ci = 0; ci < 64; ++ci) {
                    int g = ci & 3, j = ci >> 2;
                    int pad = g + 1, ks = 3 + 2 * g;
                    int t = tau - 4 - kk + pad;
                    if (t < 0 || t >= ks) continue;
                    int two = (g == 0) ? 0 : (g == 1) ? 48 : (g == 2) ? 128 : 240;
                    acc += w1s[co * 256 + ci * 4 + kk] * tws[two + j * ks + t];
                }
            }
            g_weff[cse][co][tau] = acc;
        } else {
            int r = idx - 2304;
            int kk = r >> 6, co = r & 63;
            float acc = 0.f;
            for (int ci = 0; ci < 64; ++ci)
                acc += w1s[co * 256 + ci * 4 + kk] * tbs[(ci & 3) * 16 + (ci >> 2)];
            g_tbp[kk][co] = acc;
        }
    }
}

// ---------------------------------------------------------------------------
// TT[p][co] = b1[co] + sum_{kk valid} ( tbp[kk][co] + sum_ci W1[co,ci,kk]*pe[2p-1+kk][ci] )
// ---------------------------------------------------------------------------
__global__ void tt_kernel(const float* __restrict__ cb1) {
    extern __shared__ float sm[];
    float* w1ts = sm;              // 16384
    float* pes  = sm + 16384;      // 34*64
    int tid = threadIdx.x;
    int p0 = blockIdx.x * 16;
    for (int i = tid; i < 16384; i += 256) w1ts[i] = g_w1t[i];
    for (int i = tid; i < 34 * 64; i += 256) {
        int r = i >> 6, ci = i & 63;
        int g = 2 * p0 - 1 + r;
        pes[i] = (g >= 0 && g < NL0) ? g_pe[g * 64 + ci] : 0.f;
    }
    __syncthreads();
    int co = tid & 63, py = tid >> 6;
    float acc[4] = {0.f, 0.f, 0.f, 0.f};
    for (int kk = 0; kk < 4; ++kk) {
#pragma unroll 8
        for (int ci = 0; ci < 64; ++ci) {
            float w = w1ts[(kk * 64 + ci) * 64 + co];
#pragma unroll
            for (int i = 0; i < 4; ++i)
                acc[i] += w * pes[(2 * (py * 4 + i) + kk) * 64 + ci];
        }
    }
    float tsum = g_tbp[0][co] + g_tbp[1][co] + g_tbp[2][co] + g_tbp[3][co];
    float bb = cb1[co];
#pragma unroll
    for (int i = 0; i < 4; ++i) {
        int p = p0 + py * 4 + i;
        float bias = bb + tsum;
        if (p == 0)       bias -= g_tbp[0][co];
        if (p == NL1 - 1) bias -= g_tbp[3][co];
        g_tt[p * 64 + co] = acc[i] + bias;
    }
}

// ---------------------------------------------------------------------------
// Stage1 "front": out1 = LN(tanh(conv12(Weff,x) + TT)) as bf16 hi/lo planes.
// tanh via MUFU.TANH; bf16 packing via cvt.rn.bf16x2 + bit-extract residuals.
// 256 threads, tile 128 positions, thread = 4 co x 8 pos. Grid (16, NB).
// ---------------------------------------------------------------------------
__global__ void __launch_bounds__(256)
front_kernel(const float* __restrict__ x,
             __nv_bfloat16* __restrict__ outhi, __nv_bfloat16* __restrict__ outlo,
             const float* __restrict__ lng, const float* __restrict__ lnb) {
    __shared__ float xs[266];
    __shared__ float wsm[768];
    __shared__ float gsm[64], lbsm[64];
    int tid = threadIdx.x;
    int t = blockIdx.x, b = blockIdx.y;
    int p0 = t * 128;
    if (tid < 64) { gsm[tid] = lng[tid]; lbsm[tid] = lnb[tid]; }
    for (int i = tid; i < 768; i += 256) wsm[i] = ((const float*)g_weff)[i]; // case 0
    const float* xb = x + (size_t)b * NL0;
    int base = 2 * p0 - 5;
    for (int i = tid; i < 266; i += 256) {
        int gi = base + i;
        xs[i] = (gi >= 0 && gi < NL0) ? xb[gi] : 0.f;
    }
    __syncthreads();

    int tx = tid & 15, ty = tid >> 4;
    int co0 = tx * 4;
    float wr[4][12];
#pragma unroll
    for (int c = 0; c < 4; ++c)
#pragma unroll
        for (int tau = 0; tau < 12; ++tau) wr[c][tau] = wsm[(co0 + c) * 12 + tau];
    float xr[26];
#pragma unroll
    for (int i = 0; i < 26; ++i) xr[i] = xs[16 * ty + i];

    float acc[8][4];
#pragma unroll
    for (int j = 0; j < 8; ++j) {
#pragma unroll
        for (int c = 0; c < 4; ++c) acc[j][c] = 0.f;
#pragma unroll
        for (int tau = 0; tau < 12; ++tau) {
            float xv = xr[2 * j + tau];
#pragma unroll
            for (int c = 0; c < 4; ++c) acc[j][c] = fmaf(wr[c][tau], xv, acc[j][c]);
        }
    }
    // edge positions use case-1 / case-2 composed weights
    if (t == 0 && ty == 0) {
#pragma unroll
        for (int c = 0; c < 4; ++c) {
            float a = 0.f;
            for (int tau = 0; tau < 12; ++tau) a = fmaf(g_weff[1][co0 + c][tau], xr[tau], a);
            acc[0][c] = a;
        }
    }
    if (t == 15 && ty == 15) {
#pragma unroll
        for (int c = 0; c < 4; ++c) {
            float a = 0.f;
            for (int tau = 0; tau < 12; ++tau) a = fmaf(g_weff[2][co0 + c][tau], xr[14 + tau], a);
            acc[7][c] = a;
        }
    }

    // ---- epilogue, phase-structured for ILP ----
    int pb = p0 + ty * 8;
    float4 tt[8];
#pragma unroll
    for (int j = 0; j < 8; ++j)
        tt[j] = *(const float4*)(g_tt + (pb + j) * 64 + co0);   // 8-way MLP batch

    float v[8][4];
#pragma unroll
    for (int j = 0; j < 8; ++j) {
        v[j][0] = tanh_hw(acc[j][0] + tt[j].x);
        v[j][1] = tanh_hw(acc[j][1] + tt[j].y);
        v[j][2] = tanh_hw(acc[j][2] + tt[j].z);
        v[j][3] = tanh_hw(acc[j][3] + tt[j].w);
    }
    float s1[8], s2[8];
#pragma unroll
    for (int j = 0; j < 8; ++j) {
        s1[j] = v[j][0] + v[j][1] + v[j][2] + v[j][3];
        s2[j] = v[j][0] * v[j][0] + v[j][1] * v[j][1]
              + v[j][2] * v[j][2] + v[j][3] * v[j][3];
    }
#pragma unroll
    for (int o = 1; o < 16; o <<= 1) {
#pragma unroll
        for (int j = 0; j < 8; ++j) {          // 8 independent chains per level
            s1[j] += __shfl_xor_sync(0xffffffffu, s1[j], o);
            s2[j] += __shfl_xor_sync(0xffffffffu, s2[j], o);
        }
    }
#pragma unroll
    for (int j = 0; j < 8; ++j) {
        float m   = s1[j] * (1.f / 64.f);
        float var = s2[j] * (1.f / 64.f) - m * m;
        float inv = 1.f / sqrtf(var + 1e-5f);
        float o0 = (v[j][0] - m) * inv * gsm[co0 + 0] + lbsm[co0 + 0];
        float o1 = (v[j][1] - m) * inv * gsm[co0 + 1] + lbsm[co0 + 1];
        float o2 = (v[j][2] - m) * inv * gsm[co0 + 2] + lbsm[co0 + 2];
        float o3 = (v[j][3] - m) * inv * gsm[co0 + 3] + lbsm[co0 + 3];
        size_t ro = ((size_t)b * NL1 + pb + j) * ND + co0;
        uint32_t hi01 = cvt_bf2(o0, o1);
        uint32_t hi23 = cvt_bf2(o2, o3);
        *(uint2*)(outhi + ro) = make_uint2(hi01, hi23);
        uint32_t lo01 = cvt_bf2(o0 - bf_lo_f(hi01), o1 - bf_hi_f(hi01));
        uint32_t lo23 = cvt_bf2(o2 - bf_lo_f(hi23), o3 - bf_hi_f(hi23));
        *(uint2*)(outlo + ro) = make_uint2(lo01, lo23);
    }
}

// ---------------------------------------------------------------------------
// Stages 2/3 as mma.sync bf16 GEMM; warp-private X slots (no block barriers).
// Epilogue: exact-path tanh (final-stage accuracy) + cvt.rn.bf16x2 packing.
// ---------------------------------------------------------------------------
#define X_SLOTS  544
#define X_STRIDE 144
#define SM_XHI   0
#define SM_XLO   (X_SLOTS * X_STRIDE)                 // 78,336
#define SM_WHI   (2 * X_SLOTS * X_STRIDE)             // 156,672
#define SM_WLO   (SM_WHI + 64 * 528)                  // 190,464
#define SM_F     (SM_WLO + 64 * 528)                  // 224,256
#define SMEM_BYTES (SM_F + 256 * 4)                   // 225,280

template <bool HAS_LN>
__global__ void __launch_bounds__(512, 1)
mma_stage(const __nv_bfloat16* __restrict__ inhi, const __nv_bfloat16* __restrict__ inlo,
          float* __restrict__ outf,
          __nv_bfloat16* __restrict__ outhi, __nv_bfloat16* __restrict__ outlo,
          const __nv_bfloat16* __restrict__ whi_g, const __nv_bfloat16* __restrict__ wlo_g,
          const float* __restrict__ bias, const float* __restrict__ lng,
          const float* __restrict__ lnb,
          int Lin, int Lout, int numTiles) {
    extern __shared__ char smem[];
    int tid = threadIdx.x, lane = tid & 31, wid = tid >> 5;

    {
        const uint4* s0 = (const uint4*)whi_g;
        const uint4* s1 = (const uint4*)wlo_g;
        uint4* d0 = (uint4*)(smem + SM_WHI);
        uint4* d1 = (uint4*)(smem + SM_WLO);
        for (int i = tid; i < 2112; i += 512) { d0[i] = s0[i]; d1[i] = s1[i]; }
    }
    float* fm   = (float*)(smem + SM_F);
    float* bsm  = fm;
    float* gsm  = fm + 64;
    float* lbsm = fm + 128;
    if (tid < 64) {
        bsm[tid] = bias[tid];
        if (HAS_LN) { gsm[tid] = lng[tid]; lbsm[tid] = lnb[tid]; }
    }
    __syncthreads();   // W planes + params ready (read-only afterwards)

    int warp_p0 = wid * 16;
    int arow   = lane & 15;
    int slot2  = 34 * wid + 2 * arow;                  // + kk at use
    int acib   = (lane >> 4) << 4;
    int wrow   = (lane & 7) + ((lane >> 4) << 3);
    uint32_t wbyte = (uint32_t)(wrow * 528 + (((lane >> 3) & 1) << 4));
    uint32_t xhi_b = smem_u32(smem + SM_XHI);
    uint32_t xlo_b = smem_u32(smem + SM_XLO);
    uint32_t whi_b = smem_u32(smem + SM_WHI) + wbyte;
    uint32_t wlo_b = smem_u32(smem + SM_WLO) + wbyte;

    int tilesPerB = Lout >> 8;
    for (int tile = blockIdx.x; tile < numTiles; tile += gridDim.x) {
        int b = tile / tilesPerB;
        int t = tile - b * tilesPerB;
        int p0 = t << 8;
        int g0 = 2 * p0 - 1;

        // ---- warp-private fill of this warp's 34 X rows (hi+lo planes) ----
        __syncwarp();   // prior tile's ldmatrix reads complete across lanes
        {
            const __nv_bfloat16* ihb = inhi + (size_t)b * Lin * ND;
            const __nv_bfloat16* ilb = inlo + (size_t)b * Lin * ND;
            const uint4 z4 = make_uint4(0u, 0u, 0u, 0u);
            int rbase = g0 + 32 * wid;
            for (int i = lane; i < 272; i += 32) {
                int j  = i >> 3;
                int cb = (i & 7) << 3;
                int gg = rbase + j;
                uint4 vh = z4, vl = z4;
                if (gg >= 0 && gg < Lin) {
                    size_t go = (size_t)gg * ND + cb;
                    vh = *(const uint4*)(ihb + go);
                    vl = *(const uint4*)(ilb + go);
                }
                int slot = 34 * wid + j;
                uint32_t xo = (uint32_t)(slot * X_STRIDE) +
                              (uint32_t)((cb * 2) ^ ((slot & 8) << 1));
                *(uint4*)(smem + SM_XHI + xo) = vh;
                *(uint4*)(smem + SM_XLO + xo) = vl;
            }
        }
        __syncwarp();   // fill visible to all lanes before ldmatrix

        float c[8][4];
#pragma unroll
        for (int n = 0; n < 8; ++n)
#pragma unroll
            for (int q = 0; q < 4; ++q) c[n][q] = 0.f;

#pragma unroll 2
        for (int ks = 0; ks < 16; ++ks) {
            int kk = ks >> 2;
            int slot = slot2 + kk;
            uint32_t axo = (uint32_t)(slot * X_STRIDE) +
                           (uint32_t)((((ks & 3) << 5) + acib) ^ ((slot & 8) << 1));
            uint32_t ah[4], al[4], bh[16], bl[16];
            ldsm4(ah, xhi_b + axo);
            ldsm4(al, xlo_b + axo);
            uint32_t wko = (uint32_t)(ks << 5);
            ldsm4(bh + 0,  whi_b + wko);
            ldsm4(bh + 4,  whi_b + wko + 16 * 528);
            ldsm4(bh + 8,  whi_b + wko + 32 * 528);
            ldsm4(bh + 12, whi_b + wko + 48 * 528);
            ldsm4(bl + 0,  wlo_b + wko);
            ldsm4(bl + 4,  wlo_b + wko + 16 * 528);
            ldsm4(bl + 8,  wlo_b + wko + 32 * 528);
            ldsm4(bl + 12, wlo_b + wko + 48 * 528);
#pragma unroll
            for (int g = 0; g < 4; ++g) {
                mma16816(c[2 * g],     ah, bh + 4 * g);
                mma16816(c[2 * g + 1], ah, bh + 4 * g + 2);
                mma16816(c[2 * g],     al, bh + 4 * g);
                mma16816(c[2 * g + 1], al, bh + 4 * g + 2);
                mma16816(c[2 * g],     ah, bl + 4 * g);
                mma16816(c[2 * g + 1], ah, bl + 4 * g + 2);
            }
        }

        int r0 = warp_p0 + (lane >> 2);
        int colb = (lane & 3) * 2;
        float va[16], vb[16];
#pragma unroll
        for (int n = 0; n < 8; ++n) {
            int cn = n * 8 + colb;
            va[2 * n]     = fast_tanh(c[n][0] + bsm[cn]);
            va[2 * n + 1] = fast_tanh(c[n][1] + bsm[cn + 1]);
            vb[2 * n]     = fast_tanh(c[n][2] + bsm[cn]);
            vb[2 * n + 1] = fast_tanh(c[n][3] + bsm[cn + 1]);
        }
        if (HAS_LN) {
            float s1a = 0.f, s2a = 0.f, s1b = 0.f, s2b = 0.f;
#pragma unroll
            for (int q = 0; q < 16; ++q) {
                s1a += va[q]; s2a += va[q] * va[q];
                s1b += vb[q]; s2b += vb[q] * vb[q];
            }
#pragma unroll
            for (int o = 1; o < 4; o <<= 1) {
                s1a += __shfl_xor_sync(0xffffffffu, s1a, o);
                s2a += __shfl_xor_sync(0xffffffffu, s2a, o);
                s1b += __shfl_xor_sync(0xffffffffu, s1b, o);
                s2b += __shfl_xor_sync(0xffffffffu, s2b, o);
            }
            float ma = s1a * (1.f / 64.f), mb = s1b * (1.f / 64.f);
            float ia = 1.f / sqrtf(s2a * (1.f / 64.f) - ma * ma + 1e-5f);
            float ib = 1.f / sqrtf(s2b * (1.f / 64.f) - mb * mb + 1e-5f);
            size_t rowa = (size_t)b * Lout + p0 + r0;
            __nv_bfloat16* oha = outhi + rowa * ND + colb;
            __nv_bfloat16* ola = outlo + rowa * ND + colb;
            __nv_bfloat16* ohb = oha + 8 * ND;
            __nv_bfloat16* olb = ola + 8 * ND;
#pragma unroll
            for (int n = 0; n < 8; ++n) {
                int cn = n * 8 + colb;
                float a0 = (va[2 * n]     - ma) * ia * gsm[cn]     + lbsm[cn];
                float a1 = (va[2 * n + 1] - ma) * ia * gsm[cn + 1] + lbsm[cn + 1];
                float b0 = (vb[2 * n]     - mb) * ib * gsm[cn]     + lbsm[cn];
                float b1 = (vb[2 * n + 1] - mb) * ib * gsm[cn + 1] + lbsm[cn + 1];
                uint32_t ha = cvt_bf2(a0, a1);
                uint32_t hb = cvt_bf2(b0, b1);
                *(uint32_t*)(oha + n * 8) = ha;
                *(uint32_t*)(ohb + n * 8) = hb;
                uint32_t la = cvt_bf2(a0 - bf_lo_f(ha), a1 - bf_hi_f(ha));
                uint32_t lb2v = cvt_bf2(b0 - bf_lo_f(hb), b1 - bf_hi_f(hb));
                *(uint32_t*)(ola + n * 8) = la;
                *(uint32_t*)(olb + n * 8) = lb2v;
            }
        } else {
            float* oa = outf + ((size_t)b * Lout + p0 + r0) * ND + colb;
            float* ob = oa + 8 * ND;
#pragma unroll
            for (int n = 0; n < 8; ++n) {
                *(float2*)(oa + n * 8) = make_float2(va[2 * n], va[2 * n + 1]);
                *(float2*)(ob + n * 8) = make_float2(vb[2 * n], vb[2 * n + 1]);
            }
        }
    }
}

extern "C" void kernel_launch(void* const* d_in, const int* in_sizes, int n_in,
                              void* d_out, int out_size) {
    const float* x   = (const float*)d_in[0];
    const float* tw3 = (const float*)d_in[1];
    const float* tb3 = (const float*)d_in[2];
    const float* tw5 = (const float*)d_in[3];
    const float* tb5 = (const float*)d_in[4];
    const float* tw7 = (const float*)d_in[5];
    const float* tb7 = (const float*)d_in[6];
    const float* tw9 = (const float*)d_in[7];
    const float* tb9 = (const float*)d_in[8];
    const float* cw1 = (const float*)d_in[9];
    const float* cb1 = (const float*)d_in[10];
    const float* cw2 = (const float*)d_in[11];
    const float* cb2 = (const float*)d_in[12];
    const float* cw3 = (const float*)d_in[13];
    const float* cb3 = (const float*)d_in[14];
    const float* lg1 = (const float*)d_in[15];
    const float* lb1 = (const float*)d_in[16];
    const float* lg2 = (const float*)d_in[17];
    const float* lb2 = (const float*)d_in[18];
    (void)in_sizes; (void)n_in; (void)out_size;

    void *wt_p, *h1_p, *h2_p;
    cudaGetSymbolAddress(&wt_p, g_wtb);
    cudaGetSymbolAddress(&h1_p, g_h1b);
    cudaGetSymbolAddress(&h2_p, g_h2b);
    __nv_bfloat16* wtb = (__nv_bfloat16*)wt_p;   // [3][2][64*264]
    __nv_bfloat16* h1hi = (__nv_bfloat16*)h1_p;
    __nv_bfloat16* h1lo = h1hi + (size_t)NB * NL1 * ND;
    __nv_bfloat16* h2hi = (__nv_bfloat16*)h2_p;
    __nv_bfloat16* h2lo = h2hi + (size_t)NB * NL2 * ND;

    cudaFuncSetAttribute((const void*)mma_stage<true>,
                         cudaFuncAttributeMaxDynamicSharedMemorySize, SMEM_BYTES);
    cudaFuncSetAttribute((const void*)mma_stage<false>,
                         cudaFuncAttributeMaxDynamicSharedMemorySize, SMEM_BYTES);
    const int TT_SMEM = (16384 + 34 * 64) * 4;        // 74,240 B
    cudaFuncSetAttribute((const void*)tt_kernel,
                         cudaFuncAttributeMaxDynamicSharedMemorySize, TT_SMEM);
    const int WEFF_SMEM = (16384 + 384 + 64) * 4;     // 67,328 B
    cudaFuncSetAttribute((const void*)weff_kernel,
                         cudaFuncAttributeMaxDynamicSharedMemorySize, WEFF_SMEM);

    const int PREP_N = NL0 * 32 + 32768 + 16384;
    prep_kernel<<<(PREP_N + 255) / 256, 256>>>(cw1, cw2, cw3);
    weff_kernel<<<1, 1024, WEFF_SMEM>>>(cw1, tw3, tb3, tw5, tb5, tw7, tb7, tw9, tb9);
    tt_kernel<<<128, 256, TT_SMEM>>>(cb1);

    // stage1: composed 12-tap conv + TT table -> tanh -> LN -> bf16 planes
    dim3 fg(NL1 / 128, NB);
    front_kernel<<<fg, 256>>>(x, h1hi, h1lo, lg1, lb1);

    const int PL = 64 * 264;   // bf16 elements per W plane
    mma_stage<true><<<148, 512, SMEM_BYTES>>>(
        h1hi, h1lo, nullptr, h2hi, h2lo,
        wtb + 1 * 2 * PL, wtb + (1 * 2 + 1) * PL, cb2, lg2, lb2,
        NL1, NL2, NB * (NL2 / 256));
    mma_stage<false><<<148, 512, SMEM_BYTES>>>(
        h2hi, h2lo, (float*)d_out, nullptr, nullptr,
        wtb + 2 * 2 * PL, wtb + (2 * 2 + 1) * PL, cb3, nullptr, nullptr,
        NL2, NL3, NB * (NL3 / 256));
}